// round 12
// baseline (speedup 1.0000x reference)
#include <cuda_runtime.h>
#include <cuda_bf16.h>
#include <cuda_fp16.h>
#include <cstdint>

#define N_NODES 50000
#define N_EDGES 1600000
#define IN_DIM  128
#define HID_DIM 256
#define OUT_DIM 128
#define N_PAD   (N_NODES + 128)

#define SCAN_BLK 512
#define N_SCAN_BLOCKS ((N_NODES + SCAN_BLK - 1) / SCAN_BLK)  // 98

// ---------------- device scratch (no allocations allowed) ----------------
__device__ float  g_z  [(size_t)N_NODES * OUT_DIM];   // z = h@Wr2 + b
__device__ __half g_ph [(size_t)N_NODES * OUT_DIM];   // p = h@Wl2 (fp16)
__device__ __half g_xh [(size_t)N_NODES * IN_DIM];    // x in fp16 (gather src)
// bf16 hi/lo planes for GEMM A operand (cp.async source)
__device__ __align__(16) __nv_bfloat16 g_xhi[(size_t)N_PAD * IN_DIM];
__device__ __align__(16) __nv_bfloat16 g_xlo[(size_t)N_PAD * IN_DIM];
__device__ __align__(16) __nv_bfloat16 g_mhi[(size_t)N_PAD * IN_DIM];
__device__ __align__(16) __nv_bfloat16 g_mlo[(size_t)N_PAD * IN_DIM];
__device__ int   g_deg  [N_NODES];          // zero-init; self-cleaned by scan
__device__ int   g_rowoff[N_NODES + 1];
__device__ int   g_cursor[N_NODES];
__device__ int   g_csr  [N_EDGES];
__device__ int   g_is64;
// decoupled-lookback state: (flag<<62)|value; zero-init, reset by fill_kernel.
__device__ unsigned long long g_state[N_SCAN_BLOCKS];
// pre-built B' weights: [n=256][k'=768] bf16, k' = [Bhi(256) | Blo(256) | Bhi(256)]
__device__ __align__(16) __nv_bfloat16 g_BW1[256 * 768];
__device__ __align__(16) __nv_bfloat16 g_BW2[256 * 768];

// ---------------- helpers ----------------------------------------
__device__ __forceinline__ uint32_t smem_u32(const void* p) {
    uint32_t a;
    asm("{ .reg .u64 t; cvta.to.shared.u64 t, %1; cvt.u32.u64 %0, t; }"
        : "=r"(a) : "l"(p));
    return a;
}
__device__ __forceinline__ void ldsm_x4(uint32_t* r, uint32_t addr) {
    asm volatile("ldmatrix.sync.aligned.m8n8.x4.shared.b16 {%0,%1,%2,%3}, [%4];"
        : "=r"(r[0]), "=r"(r[1]), "=r"(r[2]), "=r"(r[3]) : "r"(addr));
}
__device__ __forceinline__ void mma_bf16(float* d, const uint32_t* a, const uint32_t* b) {
    asm volatile("mma.sync.aligned.m16n8k16.row.col.f32.bf16.bf16.f32 "
        "{%0,%1,%2,%3}, {%4,%5,%6,%7}, {%8,%9}, {%0,%1,%2,%3};"
        : "+f"(d[0]), "+f"(d[1]), "+f"(d[2]), "+f"(d[3])
        : "r"(a[0]), "r"(a[1]), "r"(a[2]), "r"(a[3]), "r"(b[0]), "r"(b[1]));
}
__device__ __forceinline__ void cp_async16(uint32_t dst, const void* src) {
    asm volatile("cp.async.cg.shared.global [%0], [%1], 16;"
                 :: "r"(dst), "l"(src) : "memory");
}
#define CP_COMMIT() asm volatile("cp.async.commit_group;" ::: "memory")
#define CP_WAIT0()  asm volatile("cp.async.wait_group 0;" ::: "memory")

// packed fp32x2 add (sm_103a): acc += v, exact fp32 arithmetic, 1 instr / 2 adds
#define ADD_F32X2(acc, v) \
    asm("add.rn.f32x2 %0, %0, %1;" : "+l"(acc) : "l"(v))
__device__ __forceinline__ unsigned long long pack_f32x2(float lo, float hi) {
    unsigned long long r;
    asm("mov.b64 %0, {%1, %2};" : "=l"(r) : "f"(lo), "f"(hi));
    return r;
}
__device__ __forceinline__ float2 unpack_f32x2(unsigned long long v) {
    float lo, hi;
    asm("mov.b64 {%0, %1}, %2;" : "=f"(lo), "=f"(hi) : "l"(v));
    return make_float2(lo, hi);
}
// convert half2 pair (uint2) to two packed f32x2 values
__device__ __forceinline__ void h2x2_to_f32x2(uint2 r, unsigned long long& a,
                                              unsigned long long& b) {
    float2 fa = __half22float2(*reinterpret_cast<__half2*>(&r.x));
    float2 fb = __half22float2(*reinterpret_cast<__half2*>(&r.y));
    a = pack_f32x2(fa.x, fa.y);
    b = pack_f32x2(fb.x, fb.y);
}

// ---------------- setup + histogram (merged) -------------------------------
__global__ void setup_hist_kernel(const int* __restrict__ ei32,
                                  const float* __restrict__ x,
                                  const float* __restrict__ Wl1, const float* __restrict__ Wr1,
                                  const float* __restrict__ Wl2, const float* __restrict__ Wr2,
                                  int* __restrict__ deg,
                                  __nv_bfloat16* __restrict__ BW1,
                                  __nv_bfloat16* __restrict__ BW2,
                                  __half* __restrict__ xh,
                                  __nv_bfloat16* __restrict__ xhi,
                                  __nv_bfloat16* __restrict__ xlo) {
    int idx = blockIdx.x * blockDim.x + threadIdx.x;
    bool is64 = (ei32[1] == 0 && ei32[3] == 0 && ei32[5] == 0 && ei32[7] == 0);
    if (idx == 0) g_is64 = is64 ? 1 : 0;

    if (idx < N_EDGES / 4) {
        int i0 = idx * 4;
        int d0, d1, d2, d3;
        if (is64) {
            const longlong2* e = reinterpret_cast<const longlong2*>(
                (const long long*)ei32 + N_EDGES + i0);
            longlong2 a = e[0], b = e[1];
            d0 = (int)a.x; d1 = (int)a.y; d2 = (int)b.x; d3 = (int)b.y;
        } else {
            int4 a = *reinterpret_cast<const int4*>(ei32 + N_EDGES + i0);
            d0 = a.x; d1 = a.y; d2 = a.z; d3 = a.w;
        }
        atomicAdd(&deg[d0], 1);
        atomicAdd(&deg[d1], 1);
        atomicAdd(&deg[d2], 1);
        atomicAdd(&deg[d3], 1);
    }

    if (idx < 256 * 768) {
        int n = idx / 768, kp = idx % 768;
        int seg = kp >> 8, k = kp & 255;
        float w1 = (k < 128) ? Wl1[k * 256 + n] : Wr1[(k - 128) * 256 + n];
        float w2 = (n < 128) ? Wl2[k * 128 + n] : Wr2[k * 128 + (n - 128)];
        __nv_bfloat16 h1 = __float2bfloat16(w1);
        __nv_bfloat16 h2 = __float2bfloat16(w2);
        BW1[idx] = (seg == 1) ? __float2bfloat16(w1 - __bfloat162float(h1)) : h1;
        BW2[idx] = (seg == 1) ? __float2bfloat16(w2 - __bfloat162float(h2)) : h2;
    }
    if (idx < (N_NODES * IN_DIM) / 4) {
        float4 v = reinterpret_cast<const float4*>(x)[idx];
        __half2 a = __floats2half2_rn(v.x, v.y);
        __half2 b = __floats2half2_rn(v.z, v.w);
        reinterpret_cast<uint2*>(xh)[idx] =
            make_uint2(*reinterpret_cast<uint32_t*>(&a), *reinterpret_cast<uint32_t*>(&b));
        __nv_bfloat16 hx = __float2bfloat16(v.x), hy = __float2bfloat16(v.y);
        __nv_bfloat16 hz = __float2bfloat16(v.z), hw = __float2bfloat16(v.w);
        uint32_t hi01 = (uint32_t)__bfloat16_as_ushort(hx) |
                        ((uint32_t)__bfloat16_as_ushort(hy) << 16);
        uint32_t hi23 = (uint32_t)__bfloat16_as_ushort(hz) |
                        ((uint32_t)__bfloat16_as_ushort(hw) << 16);
        __nv_bfloat16 lx = __float2bfloat16(v.x - __bfloat162float(hx));
        __nv_bfloat16 ly = __float2bfloat16(v.y - __bfloat162float(hy));
        __nv_bfloat16 lz = __float2bfloat16(v.z - __bfloat162float(hz));
        __nv_bfloat16 lw = __float2bfloat16(v.w - __bfloat162float(hw));
        uint32_t lo01 = (uint32_t)__bfloat16_as_ushort(lx) |
                        ((uint32_t)__bfloat16_as_ushort(ly) << 16);
        uint32_t lo23 = (uint32_t)__bfloat16_as_ushort(lz) |
                        ((uint32_t)__bfloat16_as_ushort(lw) << 16);
        reinterpret_cast<uint2*>(xhi)[idx] = make_uint2(hi01, hi23);
        reinterpret_cast<uint2*>(xlo)[idx] = make_uint2(lo01, lo23);
    }
}

// ---------------- single-kernel decoupled-lookback scan --------------------
#define FLAG_AGG  (1ull << 62)
#define FLAG_INCL (2ull << 62)
#define VAL_MASK  ((1ull << 62) - 1)

__global__ __launch_bounds__(SCAN_BLK)
void scan_lookback(int* __restrict__ deg,
                   int* __restrict__ rowoff, int* __restrict__ cursor) {
    __shared__ int sm[SCAN_BLK];
    __shared__ int s_base;
    int bid = blockIdx.x, tid = threadIdx.x;
    int i = bid * SCAN_BLK + tid;
    int v = (i < N_NODES) ? deg[i] : 0;
    if (i < N_NODES) deg[i] = 0;              // self-clean for next launch
    sm[tid] = v;
    __syncthreads();
    for (int off = 1; off < SCAN_BLK; off <<= 1) {
        int u = (tid >= off) ? sm[tid - off] : 0;
        __syncthreads();
        sm[tid] += u;
        __syncthreads();
    }
    int incl = sm[tid];
    int agg = sm[SCAN_BLK - 1];
    if (tid == 0) {
        if (bid == 0) {
            atomicExch(&g_state[0], FLAG_INCL | (unsigned long long)agg);
            s_base = 0;
        } else {
            atomicExch(&g_state[bid], FLAG_AGG | (unsigned long long)agg);
            int base = 0;
            for (int j = bid - 1; j >= 0; j--) {
                unsigned long long s;
                do { s = atomicAdd(&g_state[j], 0ull); } while ((s >> 62) == 0);
                base += (int)(s & VAL_MASK);
                if ((s >> 62) == 2) break;
            }
            s_base = base;
            atomicExch(&g_state[bid],
                       FLAG_INCL | (unsigned long long)(base + agg));
        }
    }
    __syncthreads();
    int base = s_base;
    if (i < N_NODES) {
        int excl = base + incl - v;
        rowoff[i] = excl;
        cursor[i] = excl;
    }
    if (i == N_NODES - 1) rowoff[N_NODES] = base + incl;
}

// ---------------- fill CSR: 2 edges per thread; resets scan state ----------
__global__ void fill_kernel(const void* __restrict__ ei,
                            int* __restrict__ cursor, int* __restrict__ csr) {
    int t = blockIdx.x * blockDim.x + threadIdx.x;
    if (t < N_SCAN_BLOCKS) g_state[t] = 0ull;
    int i0 = t * 2;
    if (i0 >= N_EDGES) return;
    int s0, s1, d0, d1;
    if (g_is64) {
        const long long* e = (const long long*)ei;
        longlong2 sp = *reinterpret_cast<const longlong2*>(e + i0);
        longlong2 dp = *reinterpret_cast<const longlong2*>(e + N_EDGES + i0);
        s0 = (int)sp.x; s1 = (int)sp.y; d0 = (int)dp.x; d1 = (int)dp.y;
    } else {
        const int* e = (const int*)ei;
        int2 sp = *reinterpret_cast<const int2*>(e + i0);
        int2 dp = *reinterpret_cast<const int2*>(e + N_EDGES + i0);
        s0 = sp.x; s1 = sp.y; d0 = dp.x; d1 = dp.y;
    }
    csr[atomicAdd(&cursor[d0], 1)] = s0;
    csr[atomicAdd(&cursor[d1], 1)] = s1;
}

// ---------------- gather-mean: warp per node, packed f32x2 accumulation ----
__global__ __launch_bounds__(512)
void gather_mean_h(const __half* __restrict__ xh,
                   const int* __restrict__ row_off,
                   const int* __restrict__ csr,
                   __nv_bfloat16* __restrict__ mhi,
                   __nv_bfloat16* __restrict__ mlo) {
    int node = blockIdx.x * (blockDim.x >> 5) + (threadIdx.x >> 5);
    int lane = threadIdx.x & 31;
    if (node >= N_NODES) return;
    int s0 = row_off[node], s1 = row_off[node + 1];
    const uint2* x2 = reinterpret_cast<const uint2*>(xh);
    unsigned long long acc01 = pack_f32x2(0.f, 0.f);
    unsigned long long acc23 = pack_f32x2(0.f, 0.f);
    for (int j = s0; j < s1; j += 32) {
        int n = min(32, s1 - j);
        int sj = (lane < n) ? csr[j + lane] : 0;
        int t = 0;
        for (; t + 8 <= n; t += 8) {
            uint2 raw[8];
#pragma unroll
            for (int u = 0; u < 8; u++) {
                int s = __shfl_sync(0xffffffffu, sj, t + u);
                raw[u] = x2[(size_t)s * 32 + lane];
            }
#pragma unroll
            for (int u = 0; u < 8; u++) {
                unsigned long long a, b;
                h2x2_to_f32x2(raw[u], a, b);
                ADD_F32X2(acc01, a);
                ADD_F32X2(acc23, b);
            }
        }
        for (; t < n; t++) {
            int s = __shfl_sync(0xffffffffu, sj, t);
            unsigned long long a, b;
            h2x2_to_f32x2(x2[(size_t)s * 32 + lane], a, b);
            ADD_F32X2(acc01, a);
            ADD_F32X2(acc23, b);
        }
    }
    float inv = 1.0f / (float)max(s1 - s0, 1);
    float2 f01 = unpack_f32x2(acc01);
    float2 f23 = unpack_f32x2(acc23);
    float v0 = f01.x * inv, v1 = f01.y * inv, v2 = f23.x * inv, v3 = f23.y * inv;
    __nv_bfloat16 h0 = __float2bfloat16(v0), h1 = __float2bfloat16(v1);
    __nv_bfloat16 h2 = __float2bfloat16(v2), h3 = __float2bfloat16(v3);
    uint32_t hi01 = (uint32_t)__bfloat16_as_ushort(h0) |
                    ((uint32_t)__bfloat16_as_ushort(h1) << 16);
    uint32_t hi23 = (uint32_t)__bfloat16_as_ushort(h2) |
                    ((uint32_t)__bfloat16_as_ushort(h3) << 16);
    __nv_bfloat16 l0 = __float2bfloat16(v0 - __bfloat162float(h0));
    __nv_bfloat16 l1 = __float2bfloat16(v1 - __bfloat162float(h1));
    __nv_bfloat16 l2 = __float2bfloat16(v2 - __bfloat162float(h2));
    __nv_bfloat16 l3 = __float2bfloat16(v3 - __bfloat162float(h3));
    uint32_t lo01 = (uint32_t)__bfloat16_as_ushort(l0) |
                    ((uint32_t)__bfloat16_as_ushort(l1) << 16);
    uint32_t lo23 = (uint32_t)__bfloat16_as_ushort(l2) |
                    ((uint32_t)__bfloat16_as_ushort(l3) << 16);
    size_t off = (size_t)node * 32 + lane;   // uint2 units (4 bf16)
    reinterpret_cast<uint2*>(mhi)[off] = make_uint2(hi01, hi23);
    reinterpret_cast<uint2*>(mlo)[off] = make_uint2(lo01, lo23);
}

// ---------------- final gather: warp per node, packed f32x2 ----------------
__global__ __launch_bounds__(512)
void gather_final_h(const __half* __restrict__ ph,
                    const float* __restrict__ z,
                    const int* __restrict__ row_off,
                    const int* __restrict__ csr,
                    float* __restrict__ out) {
    int node = blockIdx.x * (blockDim.x >> 5) + (threadIdx.x >> 5);
    int lane = threadIdx.x & 31;
    if (node >= N_NODES) return;
    int s0 = row_off[node], s1 = row_off[node + 1];
    const uint2* p2 = reinterpret_cast<const uint2*>(ph);
    unsigned long long acc01 = pack_f32x2(0.f, 0.f);
    unsigned long long acc23 = pack_f32x2(0.f, 0.f);
    for (int j = s0; j < s1; j += 32) {
        int n = min(32, s1 - j);
        int sj = (lane < n) ? csr[j + lane] : 0;
        int t = 0;
        for (; t + 8 <= n; t += 8) {
            uint2 raw[8];
#pragma unroll
            for (int u = 0; u < 8; u++) {
                int s = __shfl_sync(0xffffffffu, sj, t + u);
                raw[u] = p2[(size_t)s * 32 + lane];
            }
#pragma unroll
            for (int u = 0; u < 8; u++) {
                unsigned long long a, b;
                h2x2_to_f32x2(raw[u], a, b);
                ADD_F32X2(acc01, a);
                ADD_F32X2(acc23, b);
            }
        }
        for (; t < n; t++) {
            int s = __shfl_sync(0xffffffffu, sj, t);
            unsigned long long a, b;
            h2x2_to_f32x2(p2[(size_t)s * 32 + lane], a, b);
            ADD_F32X2(acc01, a);
            ADD_F32X2(acc23, b);
        }
    }
    float inv = 1.0f / (float)max(s1 - s0, 1);
    float2 f01 = unpack_f32x2(acc01);
    float2 f23 = unpack_f32x2(acc23);
    float4 zv = reinterpret_cast<const float4*>(z)[(size_t)node * 32 + lane];
    float4 o = make_float4(f01.x * inv + zv.x, f01.y * inv + zv.y,
                           f23.x * inv + zv.z, f23.y * inv + zv.w);
    reinterpret_cast<float4*>(out)[(size_t)node * 32 + lane] = o;
}

// ---------------- fused layer1+layer2 GEMM ---------------------------------
#define PL_HI   0
#define PL_LO   67584
#define OFF_SA  135168             // + buf*10240  (128 rows x 80B)
#define OFF_SB  155648             // + buf*20480  (256 rows x 80B)
#define FUSED_SMEM 196608          // 192 KB

__global__ __launch_bounds__(512, 1)
void sage_fused(const __nv_bfloat16* __restrict__ Mhi, const __nv_bfloat16* __restrict__ Mlo,
                const __nv_bfloat16* __restrict__ Xhi, const __nv_bfloat16* __restrict__ Xlo,
                const __nv_bfloat16* __restrict__ BW1, const float* __restrict__ bl1,
                const __nv_bfloat16* __restrict__ BW2, const float* __restrict__ bl2,
                float* __restrict__ z, __half* __restrict__ ph, int M)
{
    extern __shared__ __align__(16) char smem[];
    uint32_t sbase = smem_u32(smem);

    int tid = threadIdx.x;
    int lane = tid & 31, wid = tid >> 5;
    int wm = wid & 3, wn = wid >> 2;
    int m0 = blockIdx.x * 128;

    int srow = tid >> 2, squad = tid & 3;

    float acc[2][8][4];
#pragma unroll
    for (int i = 0; i < 2; i++)
#pragma unroll
        for (int j = 0; j < 8; j++)
#pragma unroll
            for (int q = 0; q < 4; q++) acc[i][j][q] = 0.f;

#define CP_A1(cc, buf) do { \
    int kc = ((cc) & 7) * 32; \
    bool lo_ = ((cc) >> 3) == 2; \
    const __nv_bfloat16* src_; int col_; \
    if (kc < 128) { src_ = lo_ ? Mlo : Mhi; col_ = kc; } \
    else          { src_ = lo_ ? Xlo : Xhi; col_ = kc - 128; } \
    cp_async16(sbase + OFF_SA + (buf) * 10240 + (uint32_t)srow * 80 + squad * 16, \
               src_ + (size_t)(m0 + srow) * 128 + col_ + squad * 8); \
} while (0)

#define CP_B(BW, cc, buf) do { \
    _Pragma("unroll") \
    for (int i_ = 0; i_ < 2; i_++) { \
        int r_ = (tid >> 2) + i_ * 128; \
        cp_async16(sbase + OFF_SB + (buf) * 20480 + (uint32_t)r_ * 80 + squad * 16, \
                   (BW) + (size_t)r_ * 768 + (cc) * 32 + squad * 8); \
    } \
} while (0)

#define LOAD_FRAGS_B(buf, kh, bf) do { \
    _Pragma("unroll") \
    for (int np = 0; np < 4; np++) { \
        uint32_t q_[4]; \
        int r_ = wn * 64 + np * 16 + (lane & 7) + ((lane >> 4) & 1) * 8; \
        int cOff_ = ((lane >> 3) & 1) * 16; \
        ldsm_x4(q_, sbase + OFF_SB + (buf) * 20480 + (uint32_t)r_ * 80 + (kh) * 32 + cOff_); \
        (bf)[np * 2][0] = q_[0]; (bf)[np * 2][1] = q_[1]; \
        (bf)[np * 2 + 1][0] = q_[2]; (bf)[np * 2 + 1][1] = q_[3]; \
    } \
} while (0)

    // ================= loop 1: h = relu([mean|x] @ BW1' + bl1) ============
    CP_A1(0, 0);
    CP_B(BW1, 0, 0);
    CP_COMMIT();
    CP_WAIT0();
    __syncthreads();

    for (int c = 0; c < 24; c++) {
        int cb = c & 1;
        if (c < 23) {
            CP_A1(c + 1, cb ^ 1);
            CP_B(BW1, c + 1, cb ^ 1);
            CP_COMMIT();
        }
#pragma unroll
        for (int kh = 0; kh < 2; kh++) {
            uint32_t af[2][4], bf[8][2];
#pragma unroll
            for (int mt = 0; mt < 2; mt++)
                ldsm_x4(af[mt], sbase + OFF_SA + cb * 10240
                        + (uint32_t)(wm * 32 + mt * 16 + (lane & 15)) * 80
                        + kh * 32 + (lane >> 4) * 16);
            LOAD_FRAGS_B(cb, kh, bf);
#pragma unroll
            for (int mt = 0; mt < 2; mt++)
#pragma unroll
                for (int nt = 0; nt < 8; nt++)
                    mma_bf16(acc[mt][nt], af[mt], bf[nt]);
        }
        CP_WAIT0();
        __syncthreads();
    }

    // ---- epilogue 1: bias + relu -> bf16 hi/lo planes in SMEM ----
    {
        int g = lane >> 2, t = lane & 3;
#pragma unroll
        for (int mt = 0; mt < 2; mt++) {
            int r0 = wm * 32 + mt * 16 + g;
#pragma unroll
            for (int nt = 0; nt < 8; nt++) {
                int col = wn * 64 + nt * 8 + t * 2;
                float bx = bl1[col], by = bl1[col + 1];
                float v0 = fmaxf(acc[mt][nt][0] + bx, 0.f);
                float v1 = fmaxf(acc[mt][nt][1] + by, 0.f);
                float v2 = fmaxf(acc[mt][nt][2] + bx, 0.f);
                float v3 = fmaxf(acc[mt][nt][3] + by, 0.f);
                __nv_bfloat16 h0 = __float2bfloat16(v0), h1 = __float2bfloat16(v1);
                __nv_bfloat16 h2 = __float2bfloat16(v2), h3 = __float2bfloat16(v3);
                uint32_t hi01 = (uint32_t)__bfloat16_as_ushort(h0) |
                                ((uint32_t)__bfloat16_as_ushort(h1) << 16);
                uint32_t hi23 = (uint32_t)__bfloat16_as_ushort(h2) |
                                ((uint32_t)__bfloat16_as_ushort(h3) << 16);
                __nv_bfloat16 l0 = __float2bfloat16(v0 - __bfloat162float(h0));
                __nv_bfloat16 l1 = __float2bfloat16(v1 - __bfloat162float(h1));
                __nv_bfloat16 l2 = __float2bfloat16(v2 - __bfloat162float(h2));
                __nv_bfloat16 l3 = __float2bfloat16(v3 - __bfloat162float(h3));
                uint32_t lo01 = (uint32_t)__bfloat16_as_ushort(l0) |
                                ((uint32_t)__bfloat16_as_ushort(l1) << 16);
                uint32_t lo23 = (uint32_t)__bfloat16_as_ushort(l2) |
                                ((uint32_t)__bfloat16_as_ushort(l3) << 16);
                *reinterpret_cast<uint32_t*>(smem + PL_HI + r0 * 528 + col * 2) = hi01;
                *reinterpret_cast<uint32_t*>(smem + PL_HI + (r0 + 8) * 528 + col * 2) = hi23;
                *reinterpret_cast<uint32_t*>(smem + PL_LO + r0 * 528 + col * 2) = lo01;
                *reinterpret_cast<uint32_t*>(smem + PL_LO + (r0 + 8) * 528 + col * 2) = lo23;
            }
        }
    }

#pragma unroll
    for (int i = 0; i < 2; i++)
#pragma unroll
        for (int j = 0; j < 8; j++)
#pragma unroll
            for (int q = 0; q < 4; q++) acc[i][j][q] = 0.f;

    __syncthreads();

    // ================= loop 2: (p|z) = h_tile @ BW2' =======================
    CP_B(BW2, 0, 0);
    CP_COMMIT();
    CP_WAIT0();
    __syncthreads();

    for (int c = 0; c < 24; c++) {
        int cb = c & 1;
        if (c < 23) { CP_B(BW2, c + 1, cb ^ 1); CP_COMMIT(); }

        uint32_t plane = (c < 16) ? PL_HI : PL_LO;
        uint32_t koff = (uint32_t)(c & 7) * 64;
#pragma unroll
        for (int kh = 0; kh < 2; kh++) {
            uint32_t af[2][4], bf[8][2];
#pragma unroll
            for (int mt = 0; mt < 2; mt++)
                ldsm_x4(af[mt], sbase + plane
                        + (uint32_t)(wm * 32 + mt * 16 + (lane & 15)) * 528
                        + koff + kh * 32 + (lane >> 4) * 16);
            LOAD_FRAGS_B(cb, kh, bf);
#pragma unroll
            for (int mt = 0; mt < 2; mt++)
#pragma unroll
                for (int nt = 0; nt < 8; nt++)
                    mma_bf16(acc[mt][nt], af[mt], bf[nt]);
        }
        CP_WAIT0();
        __syncthreads();
    }

    // ---- epilogue 2 ----
    {
        int g = lane >> 2, t = lane & 3;
#pragma unroll
        for (int mt = 0; mt < 2; mt++) {
            int r0 = m0 + wm * 32 + mt * 16 + g;
#pragma unroll
            for (int nt = 0; nt < 8; nt++) {
                int col = wn * 64 + nt * 8 + t * 2;
                if (col < 128) {
                    __half2 h01 = __floats2half2_rn(acc[mt][nt][0], acc[mt][nt][1]);
                    __half2 h23 = __floats2half2_rn(acc[mt][nt][2], acc[mt][nt][3]);
                    if (r0 < M)
                        *reinterpret_cast<__half2*>(ph + (size_t)r0 * 128 + col) = h01;
                    if (r0 + 8 < M)
                        *reinterpret_cast<__half2*>(ph + (size_t)(r0 + 8) * 128 + col) = h23;
                } else {
                    int zc = col - 128;
                    float bx = bl2[zc], by = bl2[zc + 1];
                    float v0 = acc[mt][nt][0] + bx, v1 = acc[mt][nt][1] + by;
                    float v2 = acc[mt][nt][2] + bx, v3 = acc[mt][nt][3] + by;
                    if (r0 < M)
                        *reinterpret_cast<float2*>(z + (size_t)r0 * 128 + zc) = make_float2(v0, v1);
                    if (r0 + 8 < M)
                        *reinterpret_cast<float2*>(z + (size_t)(r0 + 8) * 128 + zc) = make_float2(v2, v3);
                }
            }
        }
    }
}

// ---------------- launcher -------------------------------------------------
extern "C" void kernel_launch(void* const* d_in, const int* in_sizes, int n_in,
                              void* d_out, int out_size)
{
    const float* x   = (const float*)d_in[0];
    const void*  ei  = d_in[1];
    const float* Wl1 = (const float*)d_in[2];
    const float* bl1 = (const float*)d_in[3];
    const float* Wr1 = (const float*)d_in[4];
    const float* Wl2 = (const float*)d_in[5];
    const float* bl2 = (const float*)d_in[6];
    const float* Wr2 = (const float*)d_in[7];
    float* out = (float*)d_out;

    float *z;
    __half *ph, *xh;
    __nv_bfloat16 *xhi, *xlo, *mhi, *mlo, *BW1, *BW2;
    int *deg, *rowoff, *cursor, *csr;
    cudaGetSymbolAddress((void**)&z,      g_z);
    cudaGetSymbolAddress((void**)&ph,     g_ph);
    cudaGetSymbolAddress((void**)&xh,     g_xh);
    cudaGetSymbolAddress((void**)&xhi,    g_xhi);
    cudaGetSymbolAddress((void**)&xlo,    g_xlo);
    cudaGetSymbolAddress((void**)&mhi,    g_mhi);
    cudaGetSymbolAddress((void**)&mlo,    g_mlo);
    cudaGetSymbolAddress((void**)&deg,    g_deg);
    cudaGetSymbolAddress((void**)&rowoff, g_rowoff);
    cudaGetSymbolAddress((void**)&cursor, g_cursor);
    cudaGetSymbolAddress((void**)&csr,    g_csr);
    cudaGetSymbolAddress((void**)&BW1,    g_BW1);
    cudaGetSymbolAddress((void**)&BW2,    g_BW2);

    cudaFuncSetAttribute(sage_fused, cudaFuncAttributeMaxDynamicSharedMemorySize,
                         FUSED_SMEM);

    // ---- setup + histogram (merged) ----
    {
        int nthreads = (N_NODES * IN_DIM) / 4;
        setup_hist_kernel<<<(nthreads + 255) / 256, 256>>>(
            (const int*)ei, x, Wl1, Wr1, Wl2, Wr2, deg, BW1, BW2, xh, xhi, xlo);
    }

    // ---- scan (single kernel, packed-state decoupled lookback) ----
    scan_lookback<<<N_SCAN_BLOCKS, SCAN_BLK>>>(deg, rowoff, cursor);

    // ---- fill CSR (also resets lookback state) ----
    fill_kernel<<<(N_EDGES / 2 + 255) / 256, 256>>>(ei, cursor, csr);

    // ---- layer 1 aggregation (warp per node, 512-thread blocks) ----
    {
        int wpb = 16;
        int blocks = (N_NODES + wpb - 1) / wpb;
        gather_mean_h<<<blocks, wpb * 32>>>(xh, rowoff, csr, mhi, mlo);
    }

    // ---- fused layer1+layer2 GEMM ----
    {
        int grid = (N_NODES + 127) / 128;
        sage_fused<<<grid, 512, FUSED_SMEM>>>(mhi, mlo, xhi, xlo,
                                              BW1, bl1, BW2, bl2, z, ph, N_NODES);
    }

    // ---- final aggregation (warp per node, 512-thread blocks) ----
    {
        int wpb = 16;
        int blocks = (N_NODES + wpb - 1) / wpb;
        gather_final_h<<<blocks, wpb * 32>>>(ph, z, rowoff, csr, out);
    }
}

// round 13
// speedup vs baseline: 1.0206x; 1.0206x over previous
#include <cuda_runtime.h>
#include <cuda_bf16.h>
#include <cuda_fp16.h>
#include <cstdint>

#define N_NODES 50000
#define N_EDGES 1600000
#define IN_DIM  128
#define HID_DIM 256
#define OUT_DIM 128
#define N_PAD   (N_NODES + 128)

#define SCAN_BLK 512
#define N_SCAN_BLOCKS ((N_NODES + SCAN_BLK - 1) / SCAN_BLK)  // 98

// ---------------- device scratch (no allocations allowed) ----------------
__device__ float  g_z  [(size_t)N_NODES * OUT_DIM];   // z = h@Wr2 + b
__device__ __half g_ph [(size_t)N_NODES * OUT_DIM];   // p = h@Wl2 (fp16)
__device__ __half g_xh [(size_t)N_NODES * IN_DIM];    // x in fp16 (gather src)
// bf16 hi/lo planes for GEMM A operand (cp.async source)
__device__ __align__(16) __nv_bfloat16 g_xhi[(size_t)N_PAD * IN_DIM];
__device__ __align__(16) __nv_bfloat16 g_xlo[(size_t)N_PAD * IN_DIM];
__device__ __align__(16) __nv_bfloat16 g_mhi[(size_t)N_PAD * IN_DIM];
__device__ __align__(16) __nv_bfloat16 g_mlo[(size_t)N_PAD * IN_DIM];
__device__ int   g_deg  [N_NODES];          // zero-init; self-cleaned by scan
__device__ int   g_rowoff[N_NODES + 1];
__device__ int   g_cursor[N_NODES];
__device__ int   g_csr  [N_EDGES];
__device__ int   g_is64;
// decoupled-lookback state: (flag<<62)|value; zero-init, reset by fill_kernel.
__device__ unsigned long long g_state[N_SCAN_BLOCKS];
// pre-built B' weights: [n=256][k'=768] bf16, k' = [Bhi(256) | Blo(256) | Bhi(256)]
__device__ __align__(16) __nv_bfloat16 g_BW1[256 * 768];
__device__ __align__(16) __nv_bfloat16 g_BW2[256 * 768];

// ---------------- helpers ----------------------------------------
__device__ __forceinline__ uint32_t smem_u32(const void* p) {
    uint32_t a;
    asm("{ .reg .u64 t; cvta.to.shared.u64 t, %1; cvt.u32.u64 %0, t; }"
        : "=r"(a) : "l"(p));
    return a;
}
__device__ __forceinline__ void ldsm_x4(uint32_t* r, uint32_t addr) {
    asm volatile("ldmatrix.sync.aligned.m8n8.x4.shared.b16 {%0,%1,%2,%3}, [%4];"
        : "=r"(r[0]), "=r"(r[1]), "=r"(r[2]), "=r"(r[3]) : "r"(addr));
}
__device__ __forceinline__ void mma_bf16(float* d, const uint32_t* a, const uint32_t* b) {
    asm volatile("mma.sync.aligned.m16n8k16.row.col.f32.bf16.bf16.f32 "
        "{%0,%1,%2,%3}, {%4,%5,%6,%7}, {%8,%9}, {%0,%1,%2,%3};"
        : "+f"(d[0]), "+f"(d[1]), "+f"(d[2]), "+f"(d[3])
        : "r"(a[0]), "r"(a[1]), "r"(a[2]), "r"(a[3]), "r"(b[0]), "r"(b[1]));
}
__device__ __forceinline__ void cp_async16(uint32_t dst, const void* src) {
    asm volatile("cp.async.cg.shared.global [%0], [%1], 16;"
                 :: "r"(dst), "l"(src) : "memory");
}
#define CP_COMMIT() asm volatile("cp.async.commit_group;" ::: "memory")
#define CP_WAIT0()  asm volatile("cp.async.wait_group 0;" ::: "memory")

// accumulate 8 halves (uint4) into 8 float accumulators
__device__ __forceinline__ void acc8(float* a, uint4 r) {
    float2 f0 = __half22float2(*reinterpret_cast<__half2*>(&r.x));
    float2 f1 = __half22float2(*reinterpret_cast<__half2*>(&r.y));
    float2 f2 = __half22float2(*reinterpret_cast<__half2*>(&r.z));
    float2 f3 = __half22float2(*reinterpret_cast<__half2*>(&r.w));
    a[0] += f0.x; a[1] += f0.y; a[2] += f1.x; a[3] += f1.y;
    a[4] += f2.x; a[5] += f2.y; a[6] += f3.x; a[7] += f3.y;
}

// ---------------- setup + histogram (merged) -------------------------------
__global__ void setup_hist_kernel(const int* __restrict__ ei32,
                                  const float* __restrict__ x,
                                  const float* __restrict__ Wl1, const float* __restrict__ Wr1,
                                  const float* __restrict__ Wl2, const float* __restrict__ Wr2,
                                  int* __restrict__ deg,
                                  __nv_bfloat16* __restrict__ BW1,
                                  __nv_bfloat16* __restrict__ BW2,
                                  __half* __restrict__ xh,
                                  __nv_bfloat16* __restrict__ xhi,
                                  __nv_bfloat16* __restrict__ xlo) {
    int idx = blockIdx.x * blockDim.x + threadIdx.x;
    bool is64 = (ei32[1] == 0 && ei32[3] == 0 && ei32[5] == 0 && ei32[7] == 0);
    if (idx == 0) g_is64 = is64 ? 1 : 0;

    if (idx < N_EDGES / 4) {
        int i0 = idx * 4;
        int d0, d1, d2, d3;
        if (is64) {
            const longlong2* e = reinterpret_cast<const longlong2*>(
                (const long long*)ei32 + N_EDGES + i0);
            longlong2 a = e[0], b = e[1];
            d0 = (int)a.x; d1 = (int)a.y; d2 = (int)b.x; d3 = (int)b.y;
        } else {
            int4 a = *reinterpret_cast<const int4*>(ei32 + N_EDGES + i0);
            d0 = a.x; d1 = a.y; d2 = a.z; d3 = a.w;
        }
        atomicAdd(&deg[d0], 1);
        atomicAdd(&deg[d1], 1);
        atomicAdd(&deg[d2], 1);
        atomicAdd(&deg[d3], 1);
    }

    if (idx < 256 * 768) {
        int n = idx / 768, kp = idx % 768;
        int seg = kp >> 8, k = kp & 255;
        float w1 = (k < 128) ? Wl1[k * 256 + n] : Wr1[(k - 128) * 256 + n];
        float w2 = (n < 128) ? Wl2[k * 128 + n] : Wr2[k * 128 + (n - 128)];
        __nv_bfloat16 h1 = __float2bfloat16(w1);
        __nv_bfloat16 h2 = __float2bfloat16(w2);
        BW1[idx] = (seg == 1) ? __float2bfloat16(w1 - __bfloat162float(h1)) : h1;
        BW2[idx] = (seg == 1) ? __float2bfloat16(w2 - __bfloat162float(h2)) : h2;
    }
    if (idx < (N_NODES * IN_DIM) / 4) {
        float4 v = reinterpret_cast<const float4*>(x)[idx];
        __half2 a = __floats2half2_rn(v.x, v.y);
        __half2 b = __floats2half2_rn(v.z, v.w);
        reinterpret_cast<uint2*>(xh)[idx] =
            make_uint2(*reinterpret_cast<uint32_t*>(&a), *reinterpret_cast<uint32_t*>(&b));
        __nv_bfloat16 hx = __float2bfloat16(v.x), hy = __float2bfloat16(v.y);
        __nv_bfloat16 hz = __float2bfloat16(v.z), hw = __float2bfloat16(v.w);
        uint32_t hi01 = (uint32_t)__bfloat16_as_ushort(hx) |
                        ((uint32_t)__bfloat16_as_ushort(hy) << 16);
        uint32_t hi23 = (uint32_t)__bfloat16_as_ushort(hz) |
                        ((uint32_t)__bfloat16_as_ushort(hw) << 16);
        __nv_bfloat16 lx = __float2bfloat16(v.x - __bfloat162float(hx));
        __nv_bfloat16 ly = __float2bfloat16(v.y - __bfloat162float(hy));
        __nv_bfloat16 lz = __float2bfloat16(v.z - __bfloat162float(hz));
        __nv_bfloat16 lw = __float2bfloat16(v.w - __bfloat162float(hw));
        uint32_t lo01 = (uint32_t)__bfloat16_as_ushort(lx) |
                        ((uint32_t)__bfloat16_as_ushort(ly) << 16);
        uint32_t lo23 = (uint32_t)__bfloat16_as_ushort(lz) |
                        ((uint32_t)__bfloat16_as_ushort(lw) << 16);
        reinterpret_cast<uint2*>(xhi)[idx] = make_uint2(hi01, hi23);
        reinterpret_cast<uint2*>(xlo)[idx] = make_uint2(lo01, lo23);
    }
}

// ---------------- single-kernel decoupled-lookback scan --------------------
#define FLAG_AGG  (1ull << 62)
#define FLAG_INCL (2ull << 62)
#define VAL_MASK  ((1ull << 62) - 1)

__global__ __launch_bounds__(SCAN_BLK)
void scan_lookback(int* __restrict__ deg,
                   int* __restrict__ rowoff, int* __restrict__ cursor) {
    __shared__ int sm[SCAN_BLK];
    __shared__ int s_base;
    int bid = blockIdx.x, tid = threadIdx.x;
    int i = bid * SCAN_BLK + tid;
    int v = (i < N_NODES) ? deg[i] : 0;
    if (i < N_NODES) deg[i] = 0;              // self-clean for next launch
    sm[tid] = v;
    __syncthreads();
    for (int off = 1; off < SCAN_BLK; off <<= 1) {
        int u = (tid >= off) ? sm[tid - off] : 0;
        __syncthreads();
        sm[tid] += u;
        __syncthreads();
    }
    int incl = sm[tid];
    int agg = sm[SCAN_BLK - 1];
    if (tid == 0) {
        if (bid == 0) {
            atomicExch(&g_state[0], FLAG_INCL | (unsigned long long)agg);
            s_base = 0;
        } else {
            atomicExch(&g_state[bid], FLAG_AGG | (unsigned long long)agg);
            int base = 0;
            for (int j = bid - 1; j >= 0; j--) {
                unsigned long long s;
                do { s = atomicAdd(&g_state[j], 0ull); } while ((s >> 62) == 0);
                base += (int)(s & VAL_MASK);
                if ((s >> 62) == 2) break;
            }
            s_base = base;
            atomicExch(&g_state[bid],
                       FLAG_INCL | (unsigned long long)(base + agg));
        }
    }
    __syncthreads();
    int base = s_base;
    if (i < N_NODES) {
        int excl = base + incl - v;
        rowoff[i] = excl;
        cursor[i] = excl;
    }
    if (i == N_NODES - 1) rowoff[N_NODES] = base + incl;
}

// ---------------- fill CSR: 2 edges per thread; resets scan state ----------
__global__ void fill_kernel(const void* __restrict__ ei,
                            int* __restrict__ cursor, int* __restrict__ csr) {
    int t = blockIdx.x * blockDim.x + threadIdx.x;
    if (t < N_SCAN_BLOCKS) g_state[t] = 0ull;
    int i0 = t * 2;
    if (i0 >= N_EDGES) return;
    int s0, s1, d0, d1;
    if (g_is64) {
        const long long* e = (const long long*)ei;
        longlong2 sp = *reinterpret_cast<const longlong2*>(e + i0);
        longlong2 dp = *reinterpret_cast<const longlong2*>(e + N_EDGES + i0);
        s0 = (int)sp.x; s1 = (int)sp.y; d0 = (int)dp.x; d1 = (int)dp.y;
    } else {
        const int* e = (const int*)ei;
        int2 sp = *reinterpret_cast<const int2*>(e + i0);
        int2 dp = *reinterpret_cast<const int2*>(e + N_EDGES + i0);
        s0 = sp.x; s1 = sp.y; d0 = dp.x; d1 = dp.y;
    }
    csr[atomicAdd(&cursor[d0], 1)] = s0;
    csr[atomicAdd(&cursor[d1], 1)] = s1;
}

// ---------------- gather-mean: warp per node, 2 neighbors per step ---------
// Lanes 0-15 process even neighbors, 16-31 odd neighbors — SAME node, so the
// trip count is warp-uniform. Each lane loads uint4 (8 halves = 16B).
// End: shfl_xor(16) reduction combines the two halves; lanes 0-15 write.
__global__ void gather_mean_h(const __half* __restrict__ xh,
                              const int* __restrict__ row_off,
                              const int* __restrict__ csr,
                              __nv_bfloat16* __restrict__ mhi,
                              __nv_bfloat16* __restrict__ mlo) {
    int node = blockIdx.x * (blockDim.x >> 5) + (threadIdx.x >> 5);
    int lane = threadIdx.x & 31;
    int half = lane >> 4, l16 = lane & 15;
    if (node >= N_NODES) return;
    int s0 = row_off[node], s1 = row_off[node + 1];
    const uint4* x4 = reinterpret_cast<const uint4*>(xh);   // row = 16 uint4
    float a[8] = {0.f, 0.f, 0.f, 0.f, 0.f, 0.f, 0.f, 0.f};
    for (int j = s0; j < s1; j += 32) {
        int n = min(32, s1 - j);
        int sj = (lane < n) ? csr[j + lane] : 0;
        int t = 0;
        for (; t + 8 <= n; t += 8) {
            uint4 raw[4];
#pragma unroll
            for (int u = 0; u < 4; u++) {
                int s = __shfl_sync(0xffffffffu, sj, t + u * 2 + half);
                raw[u] = x4[(size_t)s * 16 + l16];
            }
#pragma unroll
            for (int u = 0; u < 4; u++) acc8(a, raw[u]);
        }
        for (; t < n; t += 2) {
            int which = t + half;
            int s = __shfl_sync(0xffffffffu, sj, (which < n) ? which : 0);
            uint4 r = x4[(size_t)s * 16 + l16];
            if (which < n) acc8(a, r);
        }
    }
    // combine half-warp partials
#pragma unroll
    for (int q = 0; q < 8; q++)
        a[q] += __shfl_xor_sync(0xffffffffu, a[q], 16);
    if (half == 0) {
        float inv = 1.0f / (float)max(s1 - s0, 1);
        uint32_t hi[4], lo[4];
#pragma unroll
        for (int q = 0; q < 4; q++) {
            float v0 = a[q * 2] * inv, v1 = a[q * 2 + 1] * inv;
            __nv_bfloat16 h0 = __float2bfloat16(v0), h1 = __float2bfloat16(v1);
            hi[q] = (uint32_t)__bfloat16_as_ushort(h0) |
                    ((uint32_t)__bfloat16_as_ushort(h1) << 16);
            __nv_bfloat16 l0 = __float2bfloat16(v0 - __bfloat162float(h0));
            __nv_bfloat16 l1 = __float2bfloat16(v1 - __bfloat162float(h1));
            lo[q] = (uint32_t)__bfloat16_as_ushort(l0) |
                    ((uint32_t)__bfloat16_as_ushort(l1) << 16);
        }
        size_t off = (size_t)node * 16 + l16;     // uint4 units (8 bf16)
        reinterpret_cast<uint4*>(mhi)[off] = make_uint4(hi[0], hi[1], hi[2], hi[3]);
        reinterpret_cast<uint4*>(mlo)[off] = make_uint4(lo[0], lo[1], lo[2], lo[3]);
    }
}

// ---------------- final gather: warp per node, 2 neighbors per step --------
__global__ void gather_final_h(const __half* __restrict__ ph,
                               const float* __restrict__ z,
                               const int* __restrict__ row_off,
                               const int* __restrict__ csr,
                               float* __restrict__ out) {
    int node = blockIdx.x * (blockDim.x >> 5) + (threadIdx.x >> 5);
    int lane = threadIdx.x & 31;
    int half = lane >> 4, l16 = lane & 15;
    if (node >= N_NODES) return;
    int s0 = row_off[node], s1 = row_off[node + 1];
    const uint4* p4 = reinterpret_cast<const uint4*>(ph);   // row = 16 uint4
    float a[8] = {0.f, 0.f, 0.f, 0.f, 0.f, 0.f, 0.f, 0.f};
    for (int j = s0; j < s1; j += 32) {
        int n = min(32, s1 - j);
        int sj = (lane < n) ? csr[j + lane] : 0;
        int t = 0;
        for (; t + 8 <= n; t += 8) {
            uint4 raw[4];
#pragma unroll
            for (int u = 0; u < 4; u++) {
                int s = __shfl_sync(0xffffffffu, sj, t + u * 2 + half);
                raw[u] = p4[(size_t)s * 16 + l16];
            }
#pragma unroll
            for (int u = 0; u < 4; u++) acc8(a, raw[u]);
        }
        for (; t < n; t += 2) {
            int which = t + half;
            int s = __shfl_sync(0xffffffffu, sj, (which < n) ? which : 0);
            uint4 r = p4[(size_t)s * 16 + l16];
            if (which < n) acc8(a, r);
        }
    }
#pragma unroll
    for (int q = 0; q < 8; q++)
        a[q] += __shfl_xor_sync(0xffffffffu, a[q], 16);
    if (half == 0) {
        float inv = 1.0f / (float)max(s1 - s0, 1);
        size_t base = (size_t)node * 32 + l16 * 2;    // float4 units
        float4 z0 = reinterpret_cast<const float4*>(z)[base];
        float4 z1 = reinterpret_cast<const float4*>(z)[base + 1];
        float4 o0 = make_float4(a[0] * inv + z0.x, a[1] * inv + z0.y,
                                a[2] * inv + z0.z, a[3] * inv + z0.w);
        float4 o1 = make_float4(a[4] * inv + z1.x, a[5] * inv + z1.y,
                                a[6] * inv + z1.z, a[7] * inv + z1.w);
        reinterpret_cast<float4*>(out)[base] = o0;
        reinterpret_cast<float4*>(out)[base + 1] = o1;
    }
}

// ---------------- fused layer1+layer2 GEMM ---------------------------------
#define PL_HI   0
#define PL_LO   67584
#define OFF_SA  135168             // + buf*10240  (128 rows x 80B)
#define OFF_SB  155648             // + buf*20480  (256 rows x 80B)
#define FUSED_SMEM 196608          // 192 KB

__global__ __launch_bounds__(512, 1)
void sage_fused(const __nv_bfloat16* __restrict__ Mhi, const __nv_bfloat16* __restrict__ Mlo,
                const __nv_bfloat16* __restrict__ Xhi, const __nv_bfloat16* __restrict__ Xlo,
                const __nv_bfloat16* __restrict__ BW1, const float* __restrict__ bl1,
                const __nv_bfloat16* __restrict__ BW2, const float* __restrict__ bl2,
                float* __restrict__ z, __half* __restrict__ ph, int M)
{
    extern __shared__ __align__(16) char smem[];
    uint32_t sbase = smem_u32(smem);

    int tid = threadIdx.x;
    int lane = tid & 31, wid = tid >> 5;
    int wm = wid & 3, wn = wid >> 2;
    int m0 = blockIdx.x * 128;

    int srow = tid >> 2, squad = tid & 3;

    float acc[2][8][4];
#pragma unroll
    for (int i = 0; i < 2; i++)
#pragma unroll
        for (int j = 0; j < 8; j++)
#pragma unroll
            for (int q = 0; q < 4; q++) acc[i][j][q] = 0.f;

#define CP_A1(cc, buf) do { \
    int kc = ((cc) & 7) * 32; \
    bool lo_ = ((cc) >> 3) == 2; \
    const __nv_bfloat16* src_; int col_; \
    if (kc < 128) { src_ = lo_ ? Mlo : Mhi; col_ = kc; } \
    else          { src_ = lo_ ? Xlo : Xhi; col_ = kc - 128; } \
    cp_async16(sbase + OFF_SA + (buf) * 10240 + (uint32_t)srow * 80 + squad * 16, \
               src_ + (size_t)(m0 + srow) * 128 + col_ + squad * 8); \
} while (0)

#define CP_B(BW, cc, buf) do { \
    _Pragma("unroll") \
    for (int i_ = 0; i_ < 2; i_++) { \
        int r_ = (tid >> 2) + i_ * 128; \
        cp_async16(sbase + OFF_SB + (buf) * 20480 + (uint32_t)r_ * 80 + squad * 16, \
                   (BW) + (size_t)r_ * 768 + (cc) * 32 + squad * 8); \
    } \
} while (0)

#define LOAD_FRAGS_B(buf, kh, bf) do { \
    _Pragma("unroll") \
    for (int np = 0; np < 4; np++) { \
        uint32_t q_[4]; \
        int r_ = wn * 64 + np * 16 + (lane & 7) + ((lane >> 4) & 1) * 8; \
        int cOff_ = ((lane >> 3) & 1) * 16; \
        ldsm_x4(q_, sbase + OFF_SB + (buf) * 20480 + (uint32_t)r_ * 80 + (kh) * 32 + cOff_); \
        (bf)[np * 2][0] = q_[0]; (bf)[np * 2][1] = q_[1]; \
        (bf)[np * 2 + 1][0] = q_[2]; (bf)[np * 2 + 1][1] = q_[3]; \
    } \
} while (0)

    // ================= loop 1: h = relu([mean|x] @ BW1' + bl1) ============
    CP_A1(0, 0);
    CP_B(BW1, 0, 0);
    CP_COMMIT();
    CP_WAIT0();
    __syncthreads();

    for (int c = 0; c < 24; c++) {
        int cb = c & 1;
        if (c < 23) {
            CP_A1(c + 1, cb ^ 1);
            CP_B(BW1, c + 1, cb ^ 1);
            CP_COMMIT();
        }
#pragma unroll
        for (int kh = 0; kh < 2; kh++) {
            uint32_t af[2][4], bf[8][2];
#pragma unroll
            for (int mt = 0; mt < 2; mt++)
                ldsm_x4(af[mt], sbase + OFF_SA + cb * 10240
                        + (uint32_t)(wm * 32 + mt * 16 + (lane & 15)) * 80
                        + kh * 32 + (lane >> 4) * 16);
            LOAD_FRAGS_B(cb, kh, bf);
#pragma unroll
            for (int mt = 0; mt < 2; mt++)
#pragma unroll
                for (int nt = 0; nt < 8; nt++)
                    mma_bf16(acc[mt][nt], af[mt], bf[nt]);
        }
        CP_WAIT0();
        __syncthreads();
    }

    // ---- epilogue 1: bias + relu -> bf16 hi/lo planes in SMEM ----
    {
        int g = lane >> 2, t = lane & 3;
#pragma unroll
        for (int mt = 0; mt < 2; mt++) {
            int r0 = wm * 32 + mt * 16 + g;
#pragma unroll
            for (int nt = 0; nt < 8; nt++) {
                int col = wn * 64 + nt * 8 + t * 2;
                float bx = bl1[col], by = bl1[col + 1];
                float v0 = fmaxf(acc[mt][nt][0] + bx, 0.f);
                float v1 = fmaxf(acc[mt][nt][1] + by, 0.f);
                float v2 = fmaxf(acc[mt][nt][2] + bx, 0.f);
                float v3 = fmaxf(acc[mt][nt][3] + by, 0.f);
                __nv_bfloat16 h0 = __float2bfloat16(v0), h1 = __float2bfloat16(v1);
                __nv_bfloat16 h2 = __float2bfloat16(v2), h3 = __float2bfloat16(v3);
                uint32_t hi01 = (uint32_t)__bfloat16_as_ushort(h0) |
                                ((uint32_t)__bfloat16_as_ushort(h1) << 16);
                uint32_t hi23 = (uint32_t)__bfloat16_as_ushort(h2) |
                                ((uint32_t)__bfloat16_as_ushort(h3) << 16);
                __nv_bfloat16 l0 = __float2bfloat16(v0 - __bfloat162float(h0));
                __nv_bfloat16 l1 = __float2bfloat16(v1 - __bfloat162float(h1));
                __nv_bfloat16 l2 = __float2bfloat16(v2 - __bfloat162float(h2));
                __nv_bfloat16 l3 = __float2bfloat16(v3 - __bfloat162float(h3));
                uint32_t lo01 = (uint32_t)__bfloat16_as_ushort(l0) |
                                ((uint32_t)__bfloat16_as_ushort(l1) << 16);
                uint32_t lo23 = (uint32_t)__bfloat16_as_ushort(l2) |
                                ((uint32_t)__bfloat16_as_ushort(l3) << 16);
                *reinterpret_cast<uint32_t*>(smem + PL_HI + r0 * 528 + col * 2) = hi01;
                *reinterpret_cast<uint32_t*>(smem + PL_HI + (r0 + 8) * 528 + col * 2) = hi23;
                *reinterpret_cast<uint32_t*>(smem + PL_LO + r0 * 528 + col * 2) = lo01;
                *reinterpret_cast<uint32_t*>(smem + PL_LO + (r0 + 8) * 528 + col * 2) = lo23;
            }
        }
    }

#pragma unroll
    for (int i = 0; i < 2; i++)
#pragma unroll
        for (int j = 0; j < 8; j++)
#pragma unroll
            for (int q = 0; q < 4; q++) acc[i][j][q] = 0.f;

    __syncthreads();

    // ================= loop 2: (p|z) = h_tile @ BW2' =======================
    CP_B(BW2, 0, 0);
    CP_COMMIT();
    CP_WAIT0();
    __syncthreads();

    for (int c = 0; c < 24; c++) {
        int cb = c & 1;
        if (c < 23) { CP_B(BW2, c + 1, cb ^ 1); CP_COMMIT(); }

        uint32_t plane = (c < 16) ? PL_HI : PL_LO;
        uint32_t koff = (uint32_t)(c & 7) * 64;
#pragma unroll
        for (int kh = 0; kh < 2; kh++) {
            uint32_t af[2][4], bf[8][2];
#pragma unroll
            for (int mt = 0; mt < 2; mt++)
                ldsm_x4(af[mt], sbase + plane
                        + (uint32_t)(wm * 32 + mt * 16 + (lane & 15)) * 528
                        + koff + kh * 32 + (lane >> 4) * 16);
            LOAD_FRAGS_B(cb, kh, bf);
#pragma unroll
            for (int mt = 0; mt < 2; mt++)
#pragma unroll
                for (int nt = 0; nt < 8; nt++)
                    mma_bf16(acc[mt][nt], af[mt], bf[nt]);
        }
        CP_WAIT0();
        __syncthreads();
    }

    // ---- epilogue 2 ----
    {
        int g = lane >> 2, t = lane & 3;
#pragma unroll
        for (int mt = 0; mt < 2; mt++) {
            int r0 = m0 + wm * 32 + mt * 16 + g;
#pragma unroll
            for (int nt = 0; nt < 8; nt++) {
                int col = wn * 64 + nt * 8 + t * 2;
                if (col < 128) {
                    __half2 h01 = __floats2half2_rn(acc[mt][nt][0], acc[mt][nt][1]);
                    __half2 h23 = __floats2half2_rn(acc[mt][nt][2], acc[mt][nt][3]);
                    if (r0 < M)
                        *reinterpret_cast<__half2*>(ph + (size_t)r0 * 128 + col) = h01;
                    if (r0 + 8 < M)
                        *reinterpret_cast<__half2*>(ph + (size_t)(r0 + 8) * 128 + col) = h23;
                } else {
                    int zc = col - 128;
                    float bx = bl2[zc], by = bl2[zc + 1];
                    float v0 = acc[mt][nt][0] + bx, v1 = acc[mt][nt][1] + by;
                    float v2 = acc[mt][nt][2] + bx, v3 = acc[mt][nt][3] + by;
                    if (r0 < M)
                        *reinterpret_cast<float2*>(z + (size_t)r0 * 128 + zc) = make_float2(v0, v1);
                    if (r0 + 8 < M)
                        *reinterpret_cast<float2*>(z + (size_t)(r0 + 8) * 128 + zc) = make_float2(v2, v3);
                }
            }
        }
    }
}

// ---------------- launcher -------------------------------------------------
extern "C" void kernel_launch(void* const* d_in, const int* in_sizes, int n_in,
                              void* d_out, int out_size)
{
    const float* x   = (const float*)d_in[0];
    const void*  ei  = d_in[1];
    const float* Wl1 = (const float*)d_in[2];
    const float* bl1 = (const float*)d_in[3];
    const float* Wr1 = (const float*)d_in[4];
    const float* Wl2 = (const float*)d_in[5];
    const float* bl2 = (const float*)d_in[6];
    const float* Wr2 = (const float*)d_in[7];
    float* out = (float*)d_out;

    float *z;
    __half *ph, *xh;
    __nv_bfloat16 *xhi, *xlo, *mhi, *mlo, *BW1, *BW2;
    int *deg, *rowoff, *cursor, *csr;
    cudaGetSymbolAddress((void**)&z,      g_z);
    cudaGetSymbolAddress((void**)&ph,     g_ph);
    cudaGetSymbolAddress((void**)&xh,     g_xh);
    cudaGetSymbolAddress((void**)&xhi,    g_xhi);
    cudaGetSymbolAddress((void**)&xlo,    g_xlo);
    cudaGetSymbolAddress((void**)&mhi,    g_mhi);
    cudaGetSymbolAddress((void**)&mlo,    g_mlo);
    cudaGetSymbolAddress((void**)&deg,    g_deg);
    cudaGetSymbolAddress((void**)&rowoff, g_rowoff);
    cudaGetSymbolAddress((void**)&cursor, g_cursor);
    cudaGetSymbolAddress((void**)&csr,    g_csr);
    cudaGetSymbolAddress((void**)&BW1,    g_BW1);
    cudaGetSymbolAddress((void**)&BW2,    g_BW2);

    cudaFuncSetAttribute(sage_fused, cudaFuncAttributeMaxDynamicSharedMemorySize,
                         FUSED_SMEM);

    // ---- setup + histogram (merged) ----
    {
        int nthreads = (N_NODES * IN_DIM) / 4;
        setup_hist_kernel<<<(nthreads + 255) / 256, 256>>>(
            (const int*)ei, x, Wl1, Wr1, Wl2, Wr2, deg, BW1, BW2, xh, xhi, xlo);
    }

    // ---- scan (single kernel, packed-state decoupled lookback) ----
    scan_lookback<<<N_SCAN_BLOCKS, SCAN_BLK>>>(deg, rowoff, cursor);

    // ---- fill CSR (also resets lookback state) ----
    fill_kernel<<<(N_EDGES / 2 + 255) / 256, 256>>>(ei, cursor, csr);

    // ---- layer 1 aggregation (warp per node, 2 neighbors/step) ----
    {
        int wpb = 8;
        int blocks = (N_NODES + wpb - 1) / wpb;
        gather_mean_h<<<blocks, wpb * 32>>>(xh, rowoff, csr, mhi, mlo);
    }

    // ---- fused layer1+layer2 GEMM ----
    {
        int grid = (N_NODES + 127) / 128;
        sage_fused<<<grid, 512, FUSED_SMEM>>>(mhi, mlo, xhi, xlo,
                                              BW1, bl1, BW2, bl2, z, ph, N_NODES);
    }

    // ---- final aggregation (warp per node, 2 neighbors/step) ----
    {
        int wpb = 8;
        int blocks = (N_NODES + wpb - 1) / wpb;
        gather_final_h<<<blocks, wpb * 32>>>(ph, z, rowoff, csr, out);
    }
}

// round 14
// speedup vs baseline: 1.0404x; 1.0195x over previous
#include <cuda_runtime.h>
#include <cuda_bf16.h>
#include <cuda_fp16.h>
#include <cstdint>

#define N_NODES 50000
#define N_EDGES 1600000
#define IN_DIM  128
#define HID_DIM 256
#define OUT_DIM 128
#define N_PAD   (N_NODES + 128)

#define SCAN_BLK 512
#define N_SCAN_BLOCKS ((N_NODES + SCAN_BLK - 1) / SCAN_BLK)  // 98

// ---------------- device scratch (no allocations allowed) ----------------
__device__ float  g_z  [(size_t)N_NODES * OUT_DIM];   // z = h@Wr2 + b
__device__ __half g_ph [(size_t)N_NODES * OUT_DIM];   // p = h@Wl2 (fp16)
__device__ __half g_xh [(size_t)N_NODES * IN_DIM];    // x in fp16 (gather src)
// bf16 hi/lo planes for GEMM A operand (cp.async source)
__device__ __align__(16) __nv_bfloat16 g_xhi[(size_t)N_PAD * IN_DIM];
__device__ __align__(16) __nv_bfloat16 g_xlo[(size_t)N_PAD * IN_DIM];
__device__ __align__(16) __nv_bfloat16 g_mhi[(size_t)N_PAD * IN_DIM];
__device__ __align__(16) __nv_bfloat16 g_mlo[(size_t)N_PAD * IN_DIM];
__device__ int   g_deg  [N_NODES];          // zero-init; self-cleaned by scan
__device__ int   g_rank [N_EDGES];          // per-edge intra-bucket rank
__device__ int   g_rowoff[N_NODES + 1];
__device__ int   g_csr  [N_EDGES];
__device__ int   g_is64;
// decoupled-lookback state: (flag<<62)|value; zero-init, reset by fill_kernel.
__device__ unsigned long long g_state[N_SCAN_BLOCKS];
// pre-built B' weights: [n=256][k'=768] bf16, k' = [Bhi(256) | Blo(256) | Bhi(256)]
__device__ __align__(16) __nv_bfloat16 g_BW1[256 * 768];
__device__ __align__(16) __nv_bfloat16 g_BW2[256 * 768];

// ---------------- helpers ----------------------------------------
__device__ __forceinline__ uint32_t smem_u32(const void* p) {
    uint32_t a;
    asm("{ .reg .u64 t; cvta.to.shared.u64 t, %1; cvt.u32.u64 %0, t; }"
        : "=r"(a) : "l"(p));
    return a;
}
__device__ __forceinline__ void ldsm_x4(uint32_t* r, uint32_t addr) {
    asm volatile("ldmatrix.sync.aligned.m8n8.x4.shared.b16 {%0,%1,%2,%3}, [%4];"
        : "=r"(r[0]), "=r"(r[1]), "=r"(r[2]), "=r"(r[3]) : "r"(addr));
}
__device__ __forceinline__ void mma_bf16(float* d, const uint32_t* a, const uint32_t* b) {
    asm volatile("mma.sync.aligned.m16n8k16.row.col.f32.bf16.bf16.f32 "
        "{%0,%1,%2,%3}, {%4,%5,%6,%7}, {%8,%9}, {%0,%1,%2,%3};"
        : "+f"(d[0]), "+f"(d[1]), "+f"(d[2]), "+f"(d[3])
        : "r"(a[0]), "r"(a[1]), "r"(a[2]), "r"(a[3]), "r"(b[0]), "r"(b[1]));
}
__device__ __forceinline__ void cp_async16(uint32_t dst, const void* src) {
    asm volatile("cp.async.cg.shared.global [%0], [%1], 16;"
                 :: "r"(dst), "l"(src) : "memory");
}
#define CP_COMMIT() asm volatile("cp.async.commit_group;" ::: "memory")
#define CP_WAIT0()  asm volatile("cp.async.wait_group 0;" ::: "memory")

// accumulate 8 halves (uint4) into 8 float accumulators
__device__ __forceinline__ void acc8(float* a, uint4 r) {
    float2 f0 = __half22float2(*reinterpret_cast<__half2*>(&r.x));
    float2 f1 = __half22float2(*reinterpret_cast<__half2*>(&r.y));
    float2 f2 = __half22float2(*reinterpret_cast<__half2*>(&r.z));
    float2 f3 = __half22float2(*reinterpret_cast<__half2*>(&r.w));
    a[0] += f0.x; a[1] += f0.y; a[2] += f1.x; a[3] += f1.y;
    a[4] += f2.x; a[5] += f2.y; a[6] += f3.x; a[7] += f3.y;
}

// ---------------- setup + histogram (captures per-edge rank) ---------------
__global__ void setup_hist_kernel(const int* __restrict__ ei32,
                                  const float* __restrict__ x,
                                  const float* __restrict__ Wl1, const float* __restrict__ Wr1,
                                  const float* __restrict__ Wl2, const float* __restrict__ Wr2,
                                  int* __restrict__ deg,
                                  int* __restrict__ rank,
                                  __nv_bfloat16* __restrict__ BW1,
                                  __nv_bfloat16* __restrict__ BW2,
                                  __half* __restrict__ xh,
                                  __nv_bfloat16* __restrict__ xhi,
                                  __nv_bfloat16* __restrict__ xlo) {
    int idx = blockIdx.x * blockDim.x + threadIdx.x;
    bool is64 = (ei32[1] == 0 && ei32[3] == 0 && ei32[5] == 0 && ei32[7] == 0);
    if (idx == 0) g_is64 = is64 ? 1 : 0;

    if (idx < N_EDGES / 4) {
        int i0 = idx * 4;
        int d0, d1, d2, d3;
        if (is64) {
            const longlong2* e = reinterpret_cast<const longlong2*>(
                (const long long*)ei32 + N_EDGES + i0);
            longlong2 a = e[0], b = e[1];
            d0 = (int)a.x; d1 = (int)a.y; d2 = (int)b.x; d3 = (int)b.y;
        } else {
            int4 a = *reinterpret_cast<const int4*>(ei32 + N_EDGES + i0);
            d0 = a.x; d1 = a.y; d2 = a.z; d3 = a.w;
        }
        int4 rk;
        rk.x = atomicAdd(&deg[d0], 1);
        rk.y = atomicAdd(&deg[d1], 1);
        rk.z = atomicAdd(&deg[d2], 1);
        rk.w = atomicAdd(&deg[d3], 1);
        *reinterpret_cast<int4*>(rank + i0) = rk;
    }

    if (idx < 256 * 768) {
        int n = idx / 768, kp = idx % 768;
        int seg = kp >> 8, k = kp & 255;
        float w1 = (k < 128) ? Wl1[k * 256 + n] : Wr1[(k - 128) * 256 + n];
        float w2 = (n < 128) ? Wl2[k * 128 + n] : Wr2[k * 128 + (n - 128)];
        __nv_bfloat16 h1 = __float2bfloat16(w1);
        __nv_bfloat16 h2 = __float2bfloat16(w2);
        BW1[idx] = (seg == 1) ? __float2bfloat16(w1 - __bfloat162float(h1)) : h1;
        BW2[idx] = (seg == 1) ? __float2bfloat16(w2 - __bfloat162float(h2)) : h2;
    }
    if (idx < (N_NODES * IN_DIM) / 4) {
        float4 v = reinterpret_cast<const float4*>(x)[idx];
        __half2 a = __floats2half2_rn(v.x, v.y);
        __half2 b = __floats2half2_rn(v.z, v.w);
        reinterpret_cast<uint2*>(xh)[idx] =
            make_uint2(*reinterpret_cast<uint32_t*>(&a), *reinterpret_cast<uint32_t*>(&b));
        __nv_bfloat16 hx = __float2bfloat16(v.x), hy = __float2bfloat16(v.y);
        __nv_bfloat16 hz = __float2bfloat16(v.z), hw = __float2bfloat16(v.w);
        uint32_t hi01 = (uint32_t)__bfloat16_as_ushort(hx) |
                        ((uint32_t)__bfloat16_as_ushort(hy) << 16);
        uint32_t hi23 = (uint32_t)__bfloat16_as_ushort(hz) |
                        ((uint32_t)__bfloat16_as_ushort(hw) << 16);
        __nv_bfloat16 lx = __float2bfloat16(v.x - __bfloat162float(hx));
        __nv_bfloat16 ly = __float2bfloat16(v.y - __bfloat162float(hy));
        __nv_bfloat16 lz = __float2bfloat16(v.z - __bfloat162float(hz));
        __nv_bfloat16 lw = __float2bfloat16(v.w - __bfloat162float(hw));
        uint32_t lo01 = (uint32_t)__bfloat16_as_ushort(lx) |
                        ((uint32_t)__bfloat16_as_ushort(ly) << 16);
        uint32_t lo23 = (uint32_t)__bfloat16_as_ushort(lz) |
                        ((uint32_t)__bfloat16_as_ushort(lw) << 16);
        reinterpret_cast<uint2*>(xhi)[idx] = make_uint2(hi01, hi23);
        reinterpret_cast<uint2*>(xlo)[idx] = make_uint2(lo01, lo23);
    }
}

// ---------------- single-kernel decoupled-lookback scan --------------------
#define FLAG_AGG  (1ull << 62)
#define FLAG_INCL (2ull << 62)
#define VAL_MASK  ((1ull << 62) - 1)

__global__ __launch_bounds__(SCAN_BLK)
void scan_lookback(int* __restrict__ deg, int* __restrict__ rowoff) {
    __shared__ int sm[SCAN_BLK];
    __shared__ int s_base;
    int bid = blockIdx.x, tid = threadIdx.x;
    int i = bid * SCAN_BLK + tid;
    int v = (i < N_NODES) ? deg[i] : 0;
    if (i < N_NODES) deg[i] = 0;              // self-clean for next launch
    sm[tid] = v;
    __syncthreads();
    for (int off = 1; off < SCAN_BLK; off <<= 1) {
        int u = (tid >= off) ? sm[tid - off] : 0;
        __syncthreads();
        sm[tid] += u;
        __syncthreads();
    }
    int incl = sm[tid];
    int agg = sm[SCAN_BLK - 1];
    if (tid == 0) {
        if (bid == 0) {
            atomicExch(&g_state[0], FLAG_INCL | (unsigned long long)agg);
            s_base = 0;
        } else {
            atomicExch(&g_state[bid], FLAG_AGG | (unsigned long long)agg);
            int base = 0;
            for (int j = bid - 1; j >= 0; j--) {
                unsigned long long s;
                do { s = atomicAdd(&g_state[j], 0ull); } while ((s >> 62) == 0);
                base += (int)(s & VAL_MASK);
                if ((s >> 62) == 2) break;
            }
            s_base = base;
            atomicExch(&g_state[bid],
                       FLAG_INCL | (unsigned long long)(base + agg));
        }
    }
    __syncthreads();
    int base = s_base;
    if (i < N_NODES) rowoff[i] = base + incl - v;
    if (i == N_NODES - 1) rowoff[N_NODES] = base + incl;
}

// ---------------- fill CSR: atomic-free (rowoff + precomputed rank) --------
__global__ void fill_kernel(const void* __restrict__ ei,
                            const int* __restrict__ rank,
                            const int* __restrict__ rowoff,
                            int* __restrict__ csr) {
    int t = blockIdx.x * blockDim.x + threadIdx.x;
    if (t < N_SCAN_BLOCKS) g_state[t] = 0ull;   // reset lookback state
    int i0 = t * 2;
    if (i0 >= N_EDGES) return;
    int s0, s1, d0, d1;
    if (g_is64) {
        const long long* e = (const long long*)ei;
        longlong2 sp = *reinterpret_cast<const longlong2*>(e + i0);
        longlong2 dp = *reinterpret_cast<const longlong2*>(e + N_EDGES + i0);
        s0 = (int)sp.x; s1 = (int)sp.y; d0 = (int)dp.x; d1 = (int)dp.y;
    } else {
        const int* e = (const int*)ei;
        int2 sp = *reinterpret_cast<const int2*>(e + i0);
        int2 dp = *reinterpret_cast<const int2*>(e + N_EDGES + i0);
        s0 = sp.x; s1 = sp.y; d0 = dp.x; d1 = dp.y;
    }
    int2 rk = *reinterpret_cast<const int2*>(rank + i0);
    csr[rowoff[d0] + rk.x] = s0;
    csr[rowoff[d1] + rk.y] = s1;
}

// ---------------- gather-mean: warp per node, 2 neighbors per step ---------
__global__ void gather_mean_h(const __half* __restrict__ xh,
                              const int* __restrict__ row_off,
                              const int* __restrict__ csr,
                              __nv_bfloat16* __restrict__ mhi,
                              __nv_bfloat16* __restrict__ mlo) {
    int node = blockIdx.x * (blockDim.x >> 5) + (threadIdx.x >> 5);
    int lane = threadIdx.x & 31;
    int half = lane >> 4, l16 = lane & 15;
    if (node >= N_NODES) return;
    int s0 = row_off[node], s1 = row_off[node + 1];
    const uint4* x4 = reinterpret_cast<const uint4*>(xh);   // row = 16 uint4
    float a[8] = {0.f, 0.f, 0.f, 0.f, 0.f, 0.f, 0.f, 0.f};
    for (int j = s0; j < s1; j += 32) {
        int n = min(32, s1 - j);
        int sj = (lane < n) ? csr[j + lane] : 0;
        int t = 0;
        for (; t + 8 <= n; t += 8) {
            uint4 raw[4];
#pragma unroll
            for (int u = 0; u < 4; u++) {
                int s = __shfl_sync(0xffffffffu, sj, t + u * 2 + half);
                raw[u] = x4[(size_t)s * 16 + l16];
            }
#pragma unroll
            for (int u = 0; u < 4; u++) acc8(a, raw[u]);
        }
        for (; t < n; t += 2) {
            int which = t + half;
            int s = __shfl_sync(0xffffffffu, sj, (which < n) ? which : 0);
            uint4 r = x4[(size_t)s * 16 + l16];
            if (which < n) acc8(a, r);
        }
    }
#pragma unroll
    for (int q = 0; q < 8; q++)
        a[q] += __shfl_xor_sync(0xffffffffu, a[q], 16);
    if (half == 0) {
        float inv = 1.0f / (float)max(s1 - s0, 1);
        uint32_t hi[4], lo[4];
#pragma unroll
        for (int q = 0; q < 4; q++) {
            float v0 = a[q * 2] * inv, v1 = a[q * 2 + 1] * inv;
            __nv_bfloat16 h0 = __float2bfloat16(v0), h1 = __float2bfloat16(v1);
            hi[q] = (uint32_t)__bfloat16_as_ushort(h0) |
                    ((uint32_t)__bfloat16_as_ushort(h1) << 16);
            __nv_bfloat16 l0 = __float2bfloat16(v0 - __bfloat162float(h0));
            __nv_bfloat16 l1 = __float2bfloat16(v1 - __bfloat162float(h1));
            lo[q] = (uint32_t)__bfloat16_as_ushort(l0) |
                    ((uint32_t)__bfloat16_as_ushort(l1) << 16);
        }
        size_t off = (size_t)node * 16 + l16;     // uint4 units (8 bf16)
        reinterpret_cast<uint4*>(mhi)[off] = make_uint4(hi[0], hi[1], hi[2], hi[3]);
        reinterpret_cast<uint4*>(mlo)[off] = make_uint4(lo[0], lo[1], lo[2], lo[3]);
    }
}

// ---------------- final gather: warp per node, 2 neighbors per step --------
__global__ void gather_final_h(const __half* __restrict__ ph,
                               const float* __restrict__ z,
                               const int* __restrict__ row_off,
                               const int* __restrict__ csr,
                               float* __restrict__ out) {
    int node = blockIdx.x * (blockDim.x >> 5) + (threadIdx.x >> 5);
    int lane = threadIdx.x & 31;
    int half = lane >> 4, l16 = lane & 15;
    if (node >= N_NODES) return;
    int s0 = row_off[node], s1 = row_off[node + 1];
    const uint4* p4 = reinterpret_cast<const uint4*>(ph);   // row = 16 uint4
    float a[8] = {0.f, 0.f, 0.f, 0.f, 0.f, 0.f, 0.f, 0.f};
    for (int j = s0; j < s1; j += 32) {
        int n = min(32, s1 - j);
        int sj = (lane < n) ? csr[j + lane] : 0;
        int t = 0;
        for (; t + 8 <= n; t += 8) {
            uint4 raw[4];
#pragma unroll
            for (int u = 0; u < 4; u++) {
                int s = __shfl_sync(0xffffffffu, sj, t + u * 2 + half);
                raw[u] = p4[(size_t)s * 16 + l16];
            }
#pragma unroll
            for (int u = 0; u < 4; u++) acc8(a, raw[u]);
        }
        for (; t < n; t += 2) {
            int which = t + half;
            int s = __shfl_sync(0xffffffffu, sj, (which < n) ? which : 0);
            uint4 r = p4[(size_t)s * 16 + l16];
            if (which < n) acc8(a, r);
        }
    }
#pragma unroll
    for (int q = 0; q < 8; q++)
        a[q] += __shfl_xor_sync(0xffffffffu, a[q], 16);
    if (half == 0) {
        float inv = 1.0f / (float)max(s1 - s0, 1);
        size_t base = (size_t)node * 32 + l16 * 2;    // float4 units
        float4 z0 = reinterpret_cast<const float4*>(z)[base];
        float4 z1 = reinterpret_cast<const float4*>(z)[base + 1];
        float4 o0 = make_float4(a[0] * inv + z0.x, a[1] * inv + z0.y,
                                a[2] * inv + z0.z, a[3] * inv + z0.w);
        float4 o1 = make_float4(a[4] * inv + z1.x, a[5] * inv + z1.y,
                                a[6] * inv + z1.z, a[7] * inv + z1.w);
        reinterpret_cast<float4*>(out)[base] = o0;
        reinterpret_cast<float4*>(out)[base + 1] = o1;
    }
}

// ---------------- fused layer1+layer2 GEMM ---------------------------------
#define PL_HI   0
#define PL_LO   67584
#define OFF_SA  135168             // + buf*10240  (128 rows x 80B)
#define OFF_SB  155648             // + buf*20480  (256 rows x 80B)
#define FUSED_SMEM 196608          // 192 KB

__global__ __launch_bounds__(512, 1)
void sage_fused(const __nv_bfloat16* __restrict__ Mhi, const __nv_bfloat16* __restrict__ Mlo,
                const __nv_bfloat16* __restrict__ Xhi, const __nv_bfloat16* __restrict__ Xlo,
                const __nv_bfloat16* __restrict__ BW1, const float* __restrict__ bl1,
                const __nv_bfloat16* __restrict__ BW2, const float* __restrict__ bl2,
                float* __restrict__ z, __half* __restrict__ ph, int M)
{
    extern __shared__ __align__(16) char smem[];
    uint32_t sbase = smem_u32(smem);

    int tid = threadIdx.x;
    int lane = tid & 31, wid = tid >> 5;
    int wm = wid & 3, wn = wid >> 2;
    int m0 = blockIdx.x * 128;

    int srow = tid >> 2, squad = tid & 3;

    float acc[2][8][4];
#pragma unroll
    for (int i = 0; i < 2; i++)
#pragma unroll
        for (int j = 0; j < 8; j++)
#pragma unroll
            for (int q = 0; q < 4; q++) acc[i][j][q] = 0.f;

#define CP_A1(cc, buf) do { \
    int kc = ((cc) & 7) * 32; \
    bool lo_ = ((cc) >> 3) == 2; \
    const __nv_bfloat16* src_; int col_; \
    if (kc < 128) { src_ = lo_ ? Mlo : Mhi; col_ = kc; } \
    else          { src_ = lo_ ? Xlo : Xhi; col_ = kc - 128; } \
    cp_async16(sbase + OFF_SA + (buf) * 10240 + (uint32_t)srow * 80 + squad * 16, \
               src_ + (size_t)(m0 + srow) * 128 + col_ + squad * 8); \
} while (0)

#define CP_B(BW, cc, buf) do { \
    _Pragma("unroll") \
    for (int i_ = 0; i_ < 2; i_++) { \
        int r_ = (tid >> 2) + i_ * 128; \
        cp_async16(sbase + OFF_SB + (buf) * 20480 + (uint32_t)r_ * 80 + squad * 16, \
                   (BW) + (size_t)r_ * 768 + (cc) * 32 + squad * 8); \
    } \
} while (0)

#define LOAD_FRAGS_B(buf, kh, bf) do { \
    _Pragma("unroll") \
    for (int np = 0; np < 4; np++) { \
        uint32_t q_[4]; \
        int r_ = wn * 64 + np * 16 + (lane & 7) + ((lane >> 4) & 1) * 8; \
        int cOff_ = ((lane >> 3) & 1) * 16; \
        ldsm_x4(q_, sbase + OFF_SB + (buf) * 20480 + (uint32_t)r_ * 80 + (kh) * 32 + cOff_); \
        (bf)[np * 2][0] = q_[0]; (bf)[np * 2][1] = q_[1]; \
        (bf)[np * 2 + 1][0] = q_[2]; (bf)[np * 2 + 1][1] = q_[3]; \
    } \
} while (0)

    // ================= loop 1: h = relu([mean|x] @ BW1' + bl1) ============
    CP_A1(0, 0);
    CP_B(BW1, 0, 0);
    CP_COMMIT();
    CP_WAIT0();
    __syncthreads();

    for (int c = 0; c < 24; c++) {
        int cb = c & 1;
        if (c < 23) {
            CP_A1(c + 1, cb ^ 1);
            CP_B(BW1, c + 1, cb ^ 1);
            CP_COMMIT();
        }
#pragma unroll
        for (int kh = 0; kh < 2; kh++) {
            uint32_t af[2][4], bf[8][2];
#pragma unroll
            for (int mt = 0; mt < 2; mt++)
                ldsm_x4(af[mt], sbase + OFF_SA + cb * 10240
                        + (uint32_t)(wm * 32 + mt * 16 + (lane & 15)) * 80
                        + kh * 32 + (lane >> 4) * 16);
            LOAD_FRAGS_B(cb, kh, bf);
#pragma unroll
            for (int mt = 0; mt < 2; mt++)
#pragma unroll
                for (int nt = 0; nt < 8; nt++)
                    mma_bf16(acc[mt][nt], af[mt], bf[nt]);
        }
        CP_WAIT0();
        __syncthreads();
    }

    // ---- epilogue 1: bias + relu -> bf16 hi/lo planes in SMEM ----
    {
        int g = lane >> 2, t = lane & 3;
#pragma unroll
        for (int mt = 0; mt < 2; mt++) {
            int r0 = wm * 32 + mt * 16 + g;
#pragma unroll
            for (int nt = 0; nt < 8; nt++) {
                int col = wn * 64 + nt * 8 + t * 2;
                float bx = bl1[col], by = bl1[col + 1];
                float v0 = fmaxf(acc[mt][nt][0] + bx, 0.f);
                float v1 = fmaxf(acc[mt][nt][1] + by, 0.f);
                float v2 = fmaxf(acc[mt][nt][2] + bx, 0.f);
                float v3 = fmaxf(acc[mt][nt][3] + by, 0.f);
                __nv_bfloat16 h0 = __float2bfloat16(v0), h1 = __float2bfloat16(v1);
                __nv_bfloat16 h2 = __float2bfloat16(v2), h3 = __float2bfloat16(v3);
                uint32_t hi01 = (uint32_t)__bfloat16_as_ushort(h0) |
                                ((uint32_t)__bfloat16_as_ushort(h1) << 16);
                uint32_t hi23 = (uint32_t)__bfloat16_as_ushort(h2) |
                                ((uint32_t)__bfloat16_as_ushort(h3) << 16);
                __nv_bfloat16 l0 = __float2bfloat16(v0 - __bfloat162float(h0));
                __nv_bfloat16 l1 = __float2bfloat16(v1 - __bfloat162float(h1));
                __nv_bfloat16 l2 = __float2bfloat16(v2 - __bfloat162float(h2));
                __nv_bfloat16 l3 = __float2bfloat16(v3 - __bfloat162float(h3));
                uint32_t lo01 = (uint32_t)__bfloat16_as_ushort(l0) |
                                ((uint32_t)__bfloat16_as_ushort(l1) << 16);
                uint32_t lo23 = (uint32_t)__bfloat16_as_ushort(l2) |
                                ((uint32_t)__bfloat16_as_ushort(l3) << 16);
                *reinterpret_cast<uint32_t*>(smem + PL_HI + r0 * 528 + col * 2) = hi01;
                *reinterpret_cast<uint32_t*>(smem + PL_HI + (r0 + 8) * 528 + col * 2) = hi23;
                *reinterpret_cast<uint32_t*>(smem + PL_LO + r0 * 528 + col * 2) = lo01;
                *reinterpret_cast<uint32_t*>(smem + PL_LO + (r0 + 8) * 528 + col * 2) = lo23;
            }
        }
    }

#pragma unroll
    for (int i = 0; i < 2; i++)
#pragma unroll
        for (int j = 0; j < 8; j++)
#pragma unroll
            for (int q = 0; q < 4; q++) acc[i][j][q] = 0.f;

    __syncthreads();

    // ================= loop 2: (p|z) = h_tile @ BW2' =======================
    CP_B(BW2, 0, 0);
    CP_COMMIT();
    CP_WAIT0();
    __syncthreads();

    for (int c = 0; c < 24; c++) {
        int cb = c & 1;
        if (c < 23) { CP_B(BW2, c + 1, cb ^ 1); CP_COMMIT(); }

        uint32_t plane = (c < 16) ? PL_HI : PL_LO;
        uint32_t koff = (uint32_t)(c & 7) * 64;
#pragma unroll
        for (int kh = 0; kh < 2; kh++) {
            uint32_t af[2][4], bf[8][2];
#pragma unroll
            for (int mt = 0; mt < 2; mt++)
                ldsm_x4(af[mt], sbase + plane
                        + (uint32_t)(wm * 32 + mt * 16 + (lane & 15)) * 528
                        + koff + kh * 32 + (lane >> 4) * 16);
            LOAD_FRAGS_B(cb, kh, bf);
#pragma unroll
            for (int mt = 0; mt < 2; mt++)
#pragma unroll
                for (int nt = 0; nt < 8; nt++)
                    mma_bf16(acc[mt][nt], af[mt], bf[nt]);
        }
        CP_WAIT0();
        __syncthreads();
    }

    // ---- epilogue 2 ----
    {
        int g = lane >> 2, t = lane & 3;
#pragma unroll
        for (int mt = 0; mt < 2; mt++) {
            int r0 = m0 + wm * 32 + mt * 16 + g;
#pragma unroll
            for (int nt = 0; nt < 8; nt++) {
                int col = wn * 64 + nt * 8 + t * 2;
                if (col < 128) {
                    __half2 h01 = __floats2half2_rn(acc[mt][nt][0], acc[mt][nt][1]);
                    __half2 h23 = __floats2half2_rn(acc[mt][nt][2], acc[mt][nt][3]);
                    if (r0 < M)
                        *reinterpret_cast<__half2*>(ph + (size_t)r0 * 128 + col) = h01;
                    if (r0 + 8 < M)
                        *reinterpret_cast<__half2*>(ph + (size_t)(r0 + 8) * 128 + col) = h23;
                } else {
                    int zc = col - 128;
                    float bx = bl2[zc], by = bl2[zc + 1];
                    float v0 = acc[mt][nt][0] + bx, v1 = acc[mt][nt][1] + by;
                    float v2 = acc[mt][nt][2] + bx, v3 = acc[mt][nt][3] + by;
                    if (r0 < M)
                        *reinterpret_cast<float2*>(z + (size_t)r0 * 128 + zc) = make_float2(v0, v1);
                    if (r0 + 8 < M)
                        *reinterpret_cast<float2*>(z + (size_t)(r0 + 8) * 128 + zc) = make_float2(v2, v3);
                }
            }
        }
    }
}

// ---------------- launcher -------------------------------------------------
extern "C" void kernel_launch(void* const* d_in, const int* in_sizes, int n_in,
                              void* d_out, int out_size)
{
    const float* x   = (const float*)d_in[0];
    const void*  ei  = d_in[1];
    const float* Wl1 = (const float*)d_in[2];
    const float* bl1 = (const float*)d_in[3];
    const float* Wr1 = (const float*)d_in[4];
    const float* Wl2 = (const float*)d_in[5];
    const float* bl2 = (const float*)d_in[6];
    const float* Wr2 = (const float*)d_in[7];
    float* out = (float*)d_out;

    float *z;
    __half *ph, *xh;
    __nv_bfloat16 *xhi, *xlo, *mhi, *mlo, *BW1, *BW2;
    int *deg, *rank, *rowoff, *csr;
    cudaGetSymbolAddress((void**)&z,      g_z);
    cudaGetSymbolAddress((void**)&ph,     g_ph);
    cudaGetSymbolAddress((void**)&xh,     g_xh);
    cudaGetSymbolAddress((void**)&xhi,    g_xhi);
    cudaGetSymbolAddress((void**)&xlo,    g_xlo);
    cudaGetSymbolAddress((void**)&mhi,    g_mhi);
    cudaGetSymbolAddress((void**)&mlo,    g_mlo);
    cudaGetSymbolAddress((void**)&deg,    g_deg);
    cudaGetSymbolAddress((void**)&rank,   g_rank);
    cudaGetSymbolAddress((void**)&rowoff, g_rowoff);
    cudaGetSymbolAddress((void**)&csr,    g_csr);
    cudaGetSymbolAddress((void**)&BW1,    g_BW1);
    cudaGetSymbolAddress((void**)&BW2,    g_BW2);

    cudaFuncSetAttribute(sage_fused, cudaFuncAttributeMaxDynamicSharedMemorySize,
                         FUSED_SMEM);

    // ---- setup + histogram (captures per-edge rank) ----
    {
        int nthreads = (N_NODES * IN_DIM) / 4;
        setup_hist_kernel<<<(nthreads + 255) / 256, 256>>>(
            (const int*)ei, x, Wl1, Wr1, Wl2, Wr2, deg, rank, BW1, BW2, xh, xhi, xlo);
    }

    // ---- scan (single kernel, packed-state decoupled lookback) ----
    scan_lookback<<<N_SCAN_BLOCKS, SCAN_BLK>>>(deg, rowoff);

    // ---- fill CSR (atomic-free; also resets lookback state) ----
    fill_kernel<<<(N_EDGES / 2 + 255) / 256, 256>>>(ei, rank, rowoff, csr);

    // ---- layer 1 aggregation ----
    {
        int wpb = 8;
        int blocks = (N_NODES + wpb - 1) / wpb;
        gather_mean_h<<<blocks, wpb * 32>>>(xh, rowoff, csr, mhi, mlo);
    }

    // ---- fused layer1+layer2 GEMM ----
    {
        int grid = (N_NODES + 127) / 128;
        sage_fused<<<grid, 512, FUSED_SMEM>>>(mhi, mlo, xhi, xlo,
                                              BW1, bl1, BW2, bl2, z, ph, N_NODES);
    }

    // ---- final aggregation ----
    {
        int wpb = 8;
        int blocks = (N_NODES + wpb - 1) / wpb;
        gather_final_h<<<blocks, wpb * 32>>>(ph, z, rowoff, csr, out);
    }
}

// round 16
// speedup vs baseline: 1.1930x; 1.1466x over previous
#include <cuda_runtime.h>
#include <cuda_bf16.h>
#include <cuda_fp16.h>
#include <cstdint>

#define N_NODES 50000
#define N_EDGES 1600000
#define IN_DIM  128
#define HID_DIM 256
#define OUT_DIM 128
#define N_PAD   (N_NODES + 128)

#define SCAN_BLK 512
#define N_SCAN_BLOCKS ((N_NODES + SCAN_BLK - 1) / SCAN_BLK)  // 98

// ---------------- device scratch (no allocations allowed) ----------------
__device__ float  g_z  [(size_t)N_NODES * OUT_DIM];   // z = h@Wr2 + b
__device__ __half g_ph [(size_t)N_NODES * OUT_DIM];   // p = h@Wl2 (fp16)
__device__ __half g_xh [(size_t)N_NODES * IN_DIM];    // x in fp16 (gather src)
// bf16 hi/lo planes for GEMM A operand (cp.async source)
__device__ __align__(16) __nv_bfloat16 g_xhi[(size_t)N_PAD * IN_DIM];
__device__ __align__(16) __nv_bfloat16 g_xlo[(size_t)N_PAD * IN_DIM];
__device__ __align__(16) __nv_bfloat16 g_mhi[(size_t)N_PAD * IN_DIM];
__device__ __align__(16) __nv_bfloat16 g_mlo[(size_t)N_PAD * IN_DIM];
__device__ int   g_deg  [N_NODES];          // zero-init; self-cleaned by scan
__device__ int   g_rank [N_EDGES];          // per-edge intra-bucket rank
__device__ int   g_rowoff[N_NODES + 1];
__device__ int   g_csr  [N_EDGES];
__device__ int   g_is64;
// decoupled-lookback state: (flag<<62)|value; zero-init, reset by fill_kernel.
__device__ unsigned long long g_state[N_SCAN_BLOCKS];
// pre-built B' weights: [n=256][k'=768] bf16, k' = [Bhi(256) | Blo(256) | Bhi(256)]
__device__ __align__(16) __nv_bfloat16 g_BW1[256 * 768];
__device__ __align__(16) __nv_bfloat16 g_BW2[256 * 768];

// ---------------- helpers ----------------------------------------
__device__ __forceinline__ uint32_t smem_u32(const void* p) {
    uint32_t a;
    asm("{ .reg .u64 t; cvta.to.shared.u64 t, %1; cvt.u32.u64 %0, t; }"
        : "=r"(a) : "l"(p));
    return a;
}
__device__ __forceinline__ void ldsm_x4(uint32_t* r, uint32_t addr) {
    asm volatile("ldmatrix.sync.aligned.m8n8.x4.shared.b16 {%0,%1,%2,%3}, [%4];"
        : "=r"(r[0]), "=r"(r[1]), "=r"(r[2]), "=r"(r[3]) : "r"(addr));
}
__device__ __forceinline__ void mma_bf16(float* d, const uint32_t* a, const uint32_t* b) {
    asm volatile("mma.sync.aligned.m16n8k16.row.col.f32.bf16.bf16.f32 "
        "{%0,%1,%2,%3}, {%4,%5,%6,%7}, {%8,%9}, {%0,%1,%2,%3};"
        : "+f"(d[0]), "+f"(d[1]), "+f"(d[2]), "+f"(d[3])
        : "r"(a[0]), "r"(a[1]), "r"(a[2]), "r"(a[3]), "r"(b[0]), "r"(b[1]));
}
__device__ __forceinline__ void mma_f16(float* d, const uint32_t* a, const uint32_t* b) {
    asm volatile("mma.sync.aligned.m16n8k16.row.col.f32.f16.f16.f32 "
        "{%0,%1,%2,%3}, {%4,%5,%6,%7}, {%8,%9}, {%0,%1,%2,%3};"
        : "+f"(d[0]), "+f"(d[1]), "+f"(d[2]), "+f"(d[3])
        : "r"(a[0]), "r"(a[1]), "r"(a[2]), "r"(a[3]), "r"(b[0]), "r"(b[1]));
}
__device__ __forceinline__ void cp_async16(uint32_t dst, const void* src) {
    asm volatile("cp.async.cg.shared.global [%0], [%1], 16;"
                 :: "r"(dst), "l"(src) : "memory");
}
#define CP_COMMIT() asm volatile("cp.async.commit_group;" ::: "memory")
#define CP_WAIT0()  asm volatile("cp.async.wait_group 0;" ::: "memory")

// accumulate 8 halves (uint4) into 8 float accumulators
__device__ __forceinline__ void acc8(float* a, uint4 r) {
    float2 f0 = __half22float2(*reinterpret_cast<__half2*>(&r.x));
    float2 f1 = __half22float2(*reinterpret_cast<__half2*>(&r.y));
    float2 f2 = __half22float2(*reinterpret_cast<__half2*>(&r.z));
    float2 f3 = __half22float2(*reinterpret_cast<__half2*>(&r.w));
    a[0] += f0.x; a[1] += f0.y; a[2] += f1.x; a[3] += f1.y;
    a[4] += f2.x; a[5] += f2.y; a[6] += f3.x; a[7] += f3.y;
}

// ---------------- setup + histogram (captures per-edge rank) ---------------
__global__ void setup_hist_kernel(const int* __restrict__ ei32,
                                  const float* __restrict__ x,
                                  const float* __restrict__ Wl1, const float* __restrict__ Wr1,
                                  const float* __restrict__ Wl2, const float* __restrict__ Wr2,
                                  int* __restrict__ deg,
                                  int* __restrict__ rank,
                                  __nv_bfloat16* __restrict__ BW1,
                                  __nv_bfloat16* __restrict__ BW2,
                                  __half* __restrict__ xh,
                                  __nv_bfloat16* __restrict__ xhi,
                                  __nv_bfloat16* __restrict__ xlo) {
    int idx = blockIdx.x * blockDim.x + threadIdx.x;
    bool is64 = (ei32[1] == 0 && ei32[3] == 0 && ei32[5] == 0 && ei32[7] == 0);
    if (idx == 0) g_is64 = is64 ? 1 : 0;

    if (idx < N_EDGES / 4) {
        int i0 = idx * 4;
        int d0, d1, d2, d3;
        if (is64) {
            const longlong2* e = reinterpret_cast<const longlong2*>(
                (const long long*)ei32 + N_EDGES + i0);
            longlong2 a = e[0], b = e[1];
            d0 = (int)a.x; d1 = (int)a.y; d2 = (int)b.x; d3 = (int)b.y;
        } else {
            int4 a = *reinterpret_cast<const int4*>(ei32 + N_EDGES + i0);
            d0 = a.x; d1 = a.y; d2 = a.z; d3 = a.w;
        }
        int4 rk;
        rk.x = atomicAdd(&deg[d0], 1);
        rk.y = atomicAdd(&deg[d1], 1);
        rk.z = atomicAdd(&deg[d2], 1);
        rk.w = atomicAdd(&deg[d3], 1);
        *reinterpret_cast<int4*>(rank + i0) = rk;
    }

    if (idx < 256 * 768) {
        int n = idx / 768, kp = idx % 768;
        int seg = kp >> 8, k = kp & 255;
        float w1 = (k < 128) ? Wl1[k * 256 + n] : Wr1[(k - 128) * 256 + n];
        float w2 = (n < 128) ? Wl2[k * 128 + n] : Wr2[k * 128 + (n - 128)];
        __nv_bfloat16 h1 = __float2bfloat16(w1);
        __nv_bfloat16 h2 = __float2bfloat16(w2);
        BW1[idx] = (seg == 1) ? __float2bfloat16(w1 - __bfloat162float(h1)) : h1;
        BW2[idx] = (seg == 1) ? __float2bfloat16(w2 - __bfloat162float(h2)) : h2;
    }
    if (idx < (N_NODES * IN_DIM) / 4) {
        float4 v = reinterpret_cast<const float4*>(x)[idx];
        __half2 a = __floats2half2_rn(v.x, v.y);
        __half2 b = __floats2half2_rn(v.z, v.w);
        reinterpret_cast<uint2*>(xh)[idx] =
            make_uint2(*reinterpret_cast<uint32_t*>(&a), *reinterpret_cast<uint32_t*>(&b));
        __nv_bfloat16 hx = __float2bfloat16(v.x), hy = __float2bfloat16(v.y);
        __nv_bfloat16 hz = __float2bfloat16(v.z), hw = __float2bfloat16(v.w);
        uint32_t hi01 = (uint32_t)__bfloat16_as_ushort(hx) |
                        ((uint32_t)__bfloat16_as_ushort(hy) << 16);
        uint32_t hi23 = (uint32_t)__bfloat16_as_ushort(hz) |
                        ((uint32_t)__bfloat16_as_ushort(hw) << 16);
        __nv_bfloat16 lx = __float2bfloat16(v.x - __bfloat162float(hx));
        __nv_bfloat16 ly = __float2bfloat16(v.y - __bfloat162float(hy));
        __nv_bfloat16 lz = __float2bfloat16(v.z - __bfloat162float(hz));
        __nv_bfloat16 lw = __float2bfloat16(v.w - __bfloat162float(hw));
        uint32_t lo01 = (uint32_t)__bfloat16_as_ushort(lx) |
                        ((uint32_t)__bfloat16_as_ushort(ly) << 16);
        uint32_t lo23 = (uint32_t)__bfloat16_as_ushort(lz) |
                        ((uint32_t)__bfloat16_as_ushort(lw) << 16);
        reinterpret_cast<uint2*>(xhi)[idx] = make_uint2(hi01, hi23);
        reinterpret_cast<uint2*>(xlo)[idx] = make_uint2(lo01, lo23);
    }
}

// ---------------- single-kernel decoupled-lookback scan --------------------
#define FLAG_AGG  (1ull << 62)
#define FLAG_INCL (2ull << 62)
#define VAL_MASK  ((1ull << 62) - 1)

__global__ __launch_bounds__(SCAN_BLK)
void scan_lookback(int* __restrict__ deg, int* __restrict__ rowoff) {
    __shared__ int sm[SCAN_BLK];
    __shared__ int s_base;
    int bid = blockIdx.x, tid = threadIdx.x;
    int i = bid * SCAN_BLK + tid;
    int v = (i < N_NODES) ? deg[i] : 0;
    if (i < N_NODES) deg[i] = 0;              // self-clean for next launch
    sm[tid] = v;
    __syncthreads();
    for (int off = 1; off < SCAN_BLK; off <<= 1) {
        int u = (tid >= off) ? sm[tid - off] : 0;
        __syncthreads();
        sm[tid] += u;
        __syncthreads();
    }
    int incl = sm[tid];
    int agg = sm[SCAN_BLK - 1];
    if (tid == 0) {
        if (bid == 0) {
            atomicExch(&g_state[0], FLAG_INCL | (unsigned long long)agg);
            s_base = 0;
        } else {
            atomicExch(&g_state[bid], FLAG_AGG | (unsigned long long)agg);
            int base = 0;
            for (int j = bid - 1; j >= 0; j--) {
                unsigned long long s;
                do { s = atomicAdd(&g_state[j], 0ull); } while ((s >> 62) == 0);
                base += (int)(s & VAL_MASK);
                if ((s >> 62) == 2) break;
            }
            s_base = base;
            atomicExch(&g_state[bid],
                       FLAG_INCL | (unsigned long long)(base + agg));
        }
    }
    __syncthreads();
    int base = s_base;
    if (i < N_NODES) rowoff[i] = base + incl - v;
    if (i == N_NODES - 1) rowoff[N_NODES] = base + incl;
}

// ---------------- fill CSR: atomic-free (rowoff + precomputed rank) --------
__global__ void fill_kernel(const void* __restrict__ ei,
                            const int* __restrict__ rank,
                            const int* __restrict__ rowoff,
                            int* __restrict__ csr) {
    int t = blockIdx.x * blockDim.x + threadIdx.x;
    if (t < N_SCAN_BLOCKS) g_state[t] = 0ull;   // reset lookback state
    int i0 = t * 2;
    if (i0 >= N_EDGES) return;
    int s0, s1, d0, d1;
    if (g_is64) {
        const long long* e = (const long long*)ei;
        longlong2 sp = *reinterpret_cast<const longlong2*>(e + i0);
        longlong2 dp = *reinterpret_cast<const longlong2*>(e + N_EDGES + i0);
        s0 = (int)sp.x; s1 = (int)sp.y; d0 = (int)dp.x; d1 = (int)dp.y;
    } else {
        const int* e = (const int*)ei;
        int2 sp = *reinterpret_cast<const int2*>(e + i0);
        int2 dp = *reinterpret_cast<const int2*>(e + N_EDGES + i0);
        s0 = sp.x; s1 = sp.y; d0 = dp.x; d1 = dp.y;
    }
    int2 rk = *reinterpret_cast<const int2*>(rank + i0);
    csr[rowoff[d0] + rk.x] = s0;
    csr[rowoff[d1] + rk.y] = s1;
}

// ---------------- gather-mean: warp per node, 2 neighbors per step ---------
__global__ void gather_mean_h(const __half* __restrict__ xh,
                              const int* __restrict__ row_off,
                              const int* __restrict__ csr,
                              __nv_bfloat16* __restrict__ mhi,
                              __nv_bfloat16* __restrict__ mlo) {
    int node = blockIdx.x * (blockDim.x >> 5) + (threadIdx.x >> 5);
    int lane = threadIdx.x & 31;
    int half = lane >> 4, l16 = lane & 15;
    if (node >= N_NODES) return;
    int s0 = row_off[node], s1 = row_off[node + 1];
    const uint4* x4 = reinterpret_cast<const uint4*>(xh);   // row = 16 uint4
    float a[8] = {0.f, 0.f, 0.f, 0.f, 0.f, 0.f, 0.f, 0.f};
    for (int j = s0; j < s1; j += 32) {
        int n = min(32, s1 - j);
        int sj = (lane < n) ? csr[j + lane] : 0;
        int t = 0;
        for (; t + 8 <= n; t += 8) {
            uint4 raw[4];
#pragma unroll
            for (int u = 0; u < 4; u++) {
                int s = __shfl_sync(0xffffffffu, sj, t + u * 2 + half);
                raw[u] = x4[(size_t)s * 16 + l16];
            }
#pragma unroll
            for (int u = 0; u < 4; u++) acc8(a, raw[u]);
        }
        for (; t < n; t += 2) {
            int which = t + half;
            int s = __shfl_sync(0xffffffffu, sj, (which < n) ? which : 0);
            uint4 r = x4[(size_t)s * 16 + l16];
            if (which < n) acc8(a, r);
        }
    }
#pragma unroll
    for (int q = 0; q < 8; q++)
        a[q] += __shfl_xor_sync(0xffffffffu, a[q], 16);
    if (half == 0) {
        float inv = 1.0f / (float)max(s1 - s0, 1);
        uint32_t hi[4], lo[4];
#pragma unroll
        for (int q = 0; q < 4; q++) {
            float v0 = a[q * 2] * inv, v1 = a[q * 2 + 1] * inv;
            __nv_bfloat16 h0 = __float2bfloat16(v0), h1 = __float2bfloat16(v1);
            hi[q] = (uint32_t)__bfloat16_as_ushort(h0) |
                    ((uint32_t)__bfloat16_as_ushort(h1) << 16);
            __nv_bfloat16 l0 = __float2bfloat16(v0 - __bfloat162float(h0));
            __nv_bfloat16 l1 = __float2bfloat16(v1 - __bfloat162float(h1));
            lo[q] = (uint32_t)__bfloat16_as_ushort(l0) |
                    ((uint32_t)__bfloat16_as_ushort(l1) << 16);
        }
        size_t off = (size_t)node * 16 + l16;     // uint4 units (8 bf16)
        reinterpret_cast<uint4*>(mhi)[off] = make_uint4(hi[0], hi[1], hi[2], hi[3]);
        reinterpret_cast<uint4*>(mlo)[off] = make_uint4(lo[0], lo[1], lo[2], lo[3]);
    }
}

// ---------------- final gather: warp per node, 2 neighbors per step --------
__global__ void gather_final_h(const __half* __restrict__ ph,
                               const float* __restrict__ z,
                               const int* __restrict__ row_off,
                               const int* __restrict__ csr,
                               float* __restrict__ out) {
    int node = blockIdx.x * (blockDim.x >> 5) + (threadIdx.x >> 5);
    int lane = threadIdx.x & 31;
    int half = lane >> 4, l16 = lane & 15;
    if (node >= N_NODES) return;
    int s0 = row_off[node], s1 = row_off[node + 1];
    const uint4* p4 = reinterpret_cast<const uint4*>(ph);   // row = 16 uint4
    float a[8] = {0.f, 0.f, 0.f, 0.f, 0.f, 0.f, 0.f, 0.f};
    for (int j = s0; j < s1; j += 32) {
        int n = min(32, s1 - j);
        int sj = (lane < n) ? csr[j + lane] : 0;
        int t = 0;
        for (; t + 8 <= n; t += 8) {
            uint4 raw[4];
#pragma unroll
            for (int u = 0; u < 4; u++) {
                int s = __shfl_sync(0xffffffffu, sj, t + u * 2 + half);
                raw[u] = p4[(size_t)s * 16 + l16];
            }
#pragma unroll
            for (int u = 0; u < 4; u++) acc8(a, raw[u]);
        }
        for (; t < n; t += 2) {
            int which = t + half;
            int s = __shfl_sync(0xffffffffu, sj, (which < n) ? which : 0);
            uint4 r = p4[(size_t)s * 16 + l16];
            if (which < n) acc8(a, r);
        }
    }
#pragma unroll
    for (int q = 0; q < 8; q++)
        a[q] += __shfl_xor_sync(0xffffffffu, a[q], 16);
    if (half == 0) {
        float inv = 1.0f / (float)max(s1 - s0, 1);
        size_t base = (size_t)node * 32 + l16 * 2;    // float4 units
        float4 z0 = reinterpret_cast<const float4*>(z)[base];
        float4 z1 = reinterpret_cast<const float4*>(z)[base + 1];
        float4 o0 = make_float4(a[0] * inv + z0.x, a[1] * inv + z0.y,
                                a[2] * inv + z0.z, a[3] * inv + z0.w);
        float4 o1 = make_float4(a[4] * inv + z1.x, a[5] * inv + z1.y,
                                a[6] * inv + z1.z, a[7] * inv + z1.w);
        reinterpret_cast<float4*>(out)[base] = o0;
        reinterpret_cast<float4*>(out)[base + 1] = o1;
    }
}

// ---------------- fused layer1+layer2 GEMM, 64-row tiles, 2 blocks/SM ------
// 512 threads, 16 warps: wm = wid&1 (32 rows each), wn = wid>>1 (32 cols each).
// Loop1: h(64x256) = relu([mean|x]@BW1' + bl1), bf16x3 (24 chunks); h stored
// as ONE fp16 plane (2^-11 quantization). Loop2 (16 chunks, kind::f16):
// (p|z) = h_f16 @ (Bhi | Blo) — full weight precision, error only from h_f16.
#define PL_H    0                  // 64 rows x 528B = 33792
#define OFF_SA  33792              // + buf*5120   (64 rows x 80B)
#define OFF_SB  44032              // + buf*20480  (256 rows x 80B)
#define FUSED_SMEM 84992           // ~83 KB -> 2 blocks/SM

__global__ __launch_bounds__(512, 2)
void sage_fused(const __nv_bfloat16* __restrict__ Mhi, const __nv_bfloat16* __restrict__ Mlo,
                const __nv_bfloat16* __restrict__ Xhi, const __nv_bfloat16* __restrict__ Xlo,
                const __nv_bfloat16* __restrict__ BW1, const float* __restrict__ bl1,
                const __nv_bfloat16* __restrict__ BW2, const float* __restrict__ bl2,
                float* __restrict__ z, __half* __restrict__ ph, int M)
{
    extern __shared__ __align__(16) char smem[];
    uint32_t sbase = smem_u32(smem);

    int tid = threadIdx.x;
    int lane = tid & 31, wid = tid >> 5;
    int wm = wid & 1, wn = wid >> 1;        // wm: 2x32 rows, wn: 8x32 cols
    int m0 = blockIdx.x * 64;

    int srow = tid >> 2, squad = tid & 3;   // A staging uses tid<256

    float acc[2][4][4];
#pragma unroll
    for (int i = 0; i < 2; i++)
#pragma unroll
        for (int j = 0; j < 4; j++)
#pragma unroll
            for (int q = 0; q < 4; q++) acc[i][j][q] = 0.f;

#define CP_A1(cc, buf) do { \
    if (tid < 256) { \
        int kc = ((cc) & 7) * 32; \
        bool lo_ = ((cc) >> 3) == 2; \
        const __nv_bfloat16* src_; int col_; \
        if (kc < 128) { src_ = lo_ ? Mlo : Mhi; col_ = kc; } \
        else          { src_ = lo_ ? Xlo : Xhi; col_ = kc - 128; } \
        cp_async16(sbase + OFF_SA + (buf) * 5120 + (uint32_t)srow * 80 + squad * 16, \
                   src_ + (size_t)(m0 + srow) * 128 + col_ + squad * 8); \
    } \
} while (0)

#define CP_B(BW, cc, buf) do { \
    _Pragma("unroll") \
    for (int i_ = 0; i_ < 2; i_++) { \
        int r_ = (tid >> 2) + i_ * 128; \
        cp_async16(sbase + OFF_SB + (buf) * 20480 + (uint32_t)r_ * 80 + squad * 16, \
                   (BW) + (size_t)r_ * 768 + (cc) * 32 + squad * 8); \
    } \
} while (0)

// B fragments: wn covers 32 cols = 2 x ldsm_x4 (16 n-rows each)
#define LOAD_FRAGS_B(buf, kh, bf) do { \
    _Pragma("unroll") \
    for (int np = 0; np < 2; np++) { \
        uint32_t q_[4]; \
        int r_ = wn * 32 + np * 16 + (lane & 7) + ((lane >> 4) & 1) * 8; \
        int cOff_ = ((lane >> 3) & 1) * 16; \
        ldsm_x4(q_, sbase + OFF_SB + (buf) * 20480 + (uint32_t)r_ * 80 + (kh) * 32 + cOff_); \
        (bf)[np * 2][0] = q_[0]; (bf)[np * 2][1] = q_[1]; \
        (bf)[np * 2 + 1][0] = q_[2]; (bf)[np * 2 + 1][1] = q_[3]; \
    } \
} while (0)

    // ================= loop 1: h = relu([mean|x] @ BW1' + bl1) ============
    CP_A1(0, 0);
    CP_B(BW1, 0, 0);
    CP_COMMIT();
    CP_WAIT0();
    __syncthreads();

    for (int c = 0; c < 24; c++) {
        int cb = c & 1;
        if (c < 23) {
            CP_A1(c + 1, cb ^ 1);
            CP_B(BW1, c + 1, cb ^ 1);
            CP_COMMIT();
        }
#pragma unroll
        for (int kh = 0; kh < 2; kh++) {
            uint32_t af[2][4], bf[4][2];
#pragma unroll
            for (int mt = 0; mt < 2; mt++)
                ldsm_x4(af[mt], sbase + OFF_SA + cb * 5120
                        + (uint32_t)(wm * 32 + mt * 16 + (lane & 15)) * 80
                        + kh * 32 + (lane >> 4) * 16);
            LOAD_FRAGS_B(cb, kh, bf);
#pragma unroll
            for (int mt = 0; mt < 2; mt++)
#pragma unroll
                for (int nt = 0; nt < 4; nt++)
                    mma_bf16(acc[mt][nt], af[mt], bf[nt]);
        }
        CP_WAIT0();
        __syncthreads();
    }

    // ---- epilogue 1: bias + relu -> fp16 plane in SMEM ----
    {
        int g = lane >> 2, t = lane & 3;
#pragma unroll
        for (int mt = 0; mt < 2; mt++) {
            int r0 = wm * 32 + mt * 16 + g;
#pragma unroll
            for (int nt = 0; nt < 4; nt++) {
                int col = wn * 32 + nt * 8 + t * 2;
                float bx = bl1[col], by = bl1[col + 1];
                float v0 = fmaxf(acc[mt][nt][0] + bx, 0.f);
                float v1 = fmaxf(acc[mt][nt][1] + by, 0.f);
                float v2 = fmaxf(acc[mt][nt][2] + bx, 0.f);
                float v3 = fmaxf(acc[mt][nt][3] + by, 0.f);
                __half2 p01 = __floats2half2_rn(v0, v1);
                __half2 p23 = __floats2half2_rn(v2, v3);
                *reinterpret_cast<__half2*>(smem + PL_H + r0 * 528 + col * 2) = p01;
                *reinterpret_cast<__half2*>(smem + PL_H + (r0 + 8) * 528 + col * 2) = p23;
            }
        }
    }

#pragma unroll
    for (int i = 0; i < 2; i++)
#pragma unroll
        for (int j = 0; j < 4; j++)
#pragma unroll
            for (int q = 0; q < 4; q++) acc[i][j][q] = 0.f;

    __syncthreads();

    // ====== loop 2: (p|z) = h_f16 @ (Bhi | Blo)  (16 chunks, kind::f16) ====
    // B operand holds bf16 bits but is consumed with kind::f16? NO — B must
    // be fp16 too. BW2 segments 0/1 are bf16. To keep operands consistent we
    // run loop2 as kind::f16 with BOTH operands fp16: B tiles are converted
    // on the fly during staging?  Too costly. Instead: mixed is illegal, so
    // we keep A=h in bf16-style? -- RESOLVED: we pre-build BW2 in fp16 for
    // segments used by loop2. See setup: BW2 stores bf16 for loop1-style use
    // only by BW1; BW2 is consumed ONLY in loop2, so we store BW2 as fp16
    // hi/lo (hi = fp16(w), lo = fp16(w - fp16(w))). Same byte layout.
    CP_B(BW2, 0, 0);
    CP_COMMIT();
    CP_WAIT0();
    __syncthreads();

    for (int c = 0; c < 16; c++) {
        int cb = c & 1;
        if (c < 15) { CP_B(BW2, c + 1, cb ^ 1); CP_COMMIT(); }

        uint32_t koff = (uint32_t)(c & 7) * 64;
#pragma unroll
        for (int kh = 0; kh < 2; kh++) {
            uint32_t af[2][4], bf[4][2];
#pragma unroll
            for (int mt = 0; mt < 2; mt++)
                ldsm_x4(af[mt], sbase + PL_H
                        + (uint32_t)(wm * 32 + mt * 16 + (lane & 15)) * 528
                        + koff + kh * 32 + (lane >> 4) * 16);
            LOAD_FRAGS_B(cb, kh, bf);
#pragma unroll
            for (int mt = 0; mt < 2; mt++)
#pragma unroll
                for (int nt = 0; nt < 4; nt++)
                    mma_f16(acc[mt][nt], af[mt], bf[nt]);
        }
        CP_WAIT0();
        __syncthreads();
    }

    // ---- epilogue 2 ----
    {
        int g = lane >> 2, t = lane & 3;
#pragma unroll
        for (int mt = 0; mt < 2; mt++) {
            int r0 = m0 + wm * 32 + mt * 16 + g;
#pragma unroll
            for (int nt = 0; nt < 4; nt++) {
                int col = wn * 32 + nt * 8 + t * 2;
                if (col < 128) {
                    __half2 h01 = __floats2half2_rn(acc[mt][nt][0], acc[mt][nt][1]);
                    __half2 h23 = __floats2half2_rn(acc[mt][nt][2], acc[mt][nt][3]);
                    if (r0 < M)
                        *reinterpret_cast<__half2*>(ph + (size_t)r0 * 128 + col) = h01;
                    if (r0 + 8 < M)
                        *reinterpret_cast<__half2*>(ph + (size_t)(r0 + 8) * 128 + col) = h23;
                } else {
                    int zc = col - 128;
                    float bx = bl2[zc], by = bl2[zc + 1];
                    float v0 = acc[mt][nt][0] + bx, v1 = acc[mt][nt][1] + by;
                    float v2 = acc[mt][nt][2] + bx, v3 = acc[mt][nt][3] + by;
                    if (r0 < M)
                        *reinterpret_cast<float2*>(z + (size_t)r0 * 128 + zc) = make_float2(v0, v1);
                    if (r0 + 8 < M)
                        *reinterpret_cast<float2*>(z + (size_t)(r0 + 8) * 128 + zc) = make_float2(v2, v3);
                }
            }
        }
    }
}

// BW2 is consumed only by loop 2 (kind::f16), so store it as fp16 hi/lo.
__global__ void prep_bw2_f16(const float* __restrict__ Wl2,
                             const float* __restrict__ Wr2,
                             __half* __restrict__ BW2h) {
    int idx = blockIdx.x * blockDim.x + threadIdx.x;   // n*768 + kp (seg 0/1 only)
    if (idx >= 256 * 768) return;
    int n = idx / 768, kp = idx % 768;
    int seg = kp >> 8, k = kp & 255;
    if (seg == 2) { BW2h[idx] = __float2half(0.f); return; }
    float w2 = (n < 128) ? Wl2[k * 128 + n] : Wr2[k * 128 + (n - 128)];
    __half h = __float2half(w2);
    BW2h[idx] = (seg == 1) ? __float2half(w2 - __half2float(h)) : h;
}

// ---------------- launcher -------------------------------------------------
extern "C" void kernel_launch(void* const* d_in, const int* in_sizes, int n_in,
                              void* d_out, int out_size)
{
    const float* x   = (const float*)d_in[0];
    const void*  ei  = d_in[1];
    const float* Wl1 = (const float*)d_in[2];
    const float* bl1 = (const float*)d_in[3];
    const float* Wr1 = (const float*)d_in[4];
    const float* Wl2 = (const float*)d_in[5];
    const float* bl2 = (const float*)d_in[6];
    const float* Wr2 = (const float*)d_in[7];
    float* out = (float*)d_out;

    float *z;
    __half *ph, *xh;
    __nv_bfloat16 *xhi, *xlo, *mhi, *mlo, *BW1, *BW2;
    int *deg, *rank, *rowoff, *csr;
    cudaGetSymbolAddress((void**)&z,      g_z);
    cudaGetSymbolAddress((void**)&ph,     g_ph);
    cudaGetSymbolAddress((void**)&xh,     g_xh);
    cudaGetSymbolAddress((void**)&xhi,    g_xhi);
    cudaGetSymbolAddress((void**)&xlo,    g_xlo);
    cudaGetSymbolAddress((void**)&mhi,    g_mhi);
    cudaGetSymbolAddress((void**)&mlo,    g_mlo);
    cudaGetSymbolAddress((void**)&deg,    g_deg);
    cudaGetSymbolAddress((void**)&rank,   g_rank);
    cudaGetSymbolAddress((void**)&rowoff, g_rowoff);
    cudaGetSymbolAddress((void**)&csr,    g_csr);
    cudaGetSymbolAddress((void**)&BW1,    g_BW1);
    cudaGetSymbolAddress((void**)&BW2,    g_BW2);

    cudaFuncSetAttribute(sage_fused, cudaFuncAttributeMaxDynamicSharedMemorySize,
                         FUSED_SMEM);

    // ---- setup + histogram (captures per-edge rank) ----
    {
        int nthreads = (N_NODES * IN_DIM) / 4;
        setup_hist_kernel<<<(nthreads + 255) / 256, 256>>>(
            (const int*)ei, x, Wl1, Wr1, Wl2, Wr2, deg, rank, BW1, BW2, xh, xhi, xlo);
    }
    // overwrite BW2 with fp16 hi/lo (loop-2 operand, kind::f16)
    prep_bw2_f16<<<(256 * 768 + 255) / 256, 256>>>(Wl2, Wr2, (__half*)BW2);

    // ---- scan (single kernel, packed-state decoupled lookback) ----
    scan_lookback<<<N_SCAN_BLOCKS, SCAN_BLK>>>(deg, rowoff);

    // ---- fill CSR (atomic-free; also resets lookback state) ----
    fill_kernel<<<(N_EDGES / 2 + 255) / 256, 256>>>(ei, rank, rowoff, csr);

    // ---- layer 1 aggregation ----
    {
        int wpb = 8;
        int blocks = (N_NODES + wpb - 1) / wpb;
        gather_mean_h<<<blocks, wpb * 32>>>(xh, rowoff, csr, mhi, mlo);
    }

    // ---- fused layer1+layer2 GEMM (64-row tiles, 2 blocks/SM) ----
    {
        int grid = (N_NODES + 63) / 64;
        sage_fused<<<grid, 512, FUSED_SMEM>>>(mhi, mlo, xhi, xlo,
                                              BW1, bl1, BW2, bl2, z, ph, N_NODES);
    }

    // ---- final aggregation ----
    {
        int wpb = 8;
        int blocks = (N_NODES + wpb - 1) / wpb;
        gather_final_h<<<blocks, wpb * 32>>>(ph, z, rowoff, csr, out);
    }
}

// round 17
// speedup vs baseline: 1.4006x; 1.1740x over previous
#include <cuda_runtime.h>
#include <cuda_bf16.h>
#include <cuda_fp16.h>
#include <cstdint>

#define N_NODES 50000
#define N_EDGES 1600000
#define IN_DIM  128
#define HID_DIM 256
#define OUT_DIM 128
#define N_PAD   (N_NODES + 128)

#define SCAN_BLK 512
#define N_SCAN_BLOCKS ((N_NODES + SCAN_BLK - 1) / SCAN_BLK)  // 98

// ---------------- device scratch (no allocations allowed) ----------------
__device__ float  g_z  [(size_t)N_NODES * OUT_DIM];   // z = h@Wr2 + b
__device__ __half g_ph [(size_t)N_NODES * OUT_DIM];   // p = h@Wl2 (fp16)
__device__ __half g_xh [(size_t)N_NODES * IN_DIM];    // x in fp16 (gather + GEMM A)
__device__ __align__(16) __half g_mh [(size_t)N_PAD * IN_DIM];  // mean in fp16 (GEMM A)
__device__ int   g_deg  [N_NODES];          // zero-init; self-cleaned by scan
__device__ int   g_rank [N_EDGES];          // per-edge intra-bucket rank
__device__ int   g_rowoff[N_NODES + 1];
__device__ int   g_csr  [N_EDGES];
__device__ int   g_is64;
// decoupled-lookback state: (flag<<62)|value; zero-init, reset by fill_kernel.
__device__ unsigned long long g_state[N_SCAN_BLOCKS];
// pre-built weights, fp16 hi/lo: [n=256][k'=512], k' = [Whi(256) | Wlo(256)]
__device__ __align__(16) __half g_BW1[256 * 512];
__device__ __align__(16) __half g_BW2[256 * 512];

// ---------------- helpers ----------------------------------------
__device__ __forceinline__ uint32_t smem_u32(const void* p) {
    uint32_t a;
    asm("{ .reg .u64 t; cvta.to.shared.u64 t, %1; cvt.u32.u64 %0, t; }"
        : "=r"(a) : "l"(p));
    return a;
}
__device__ __forceinline__ void ldsm_x4(uint32_t* r, uint32_t addr) {
    asm volatile("ldmatrix.sync.aligned.m8n8.x4.shared.b16 {%0,%1,%2,%3}, [%4];"
        : "=r"(r[0]), "=r"(r[1]), "=r"(r[2]), "=r"(r[3]) : "r"(addr));
}
__device__ __forceinline__ void mma_f16(float* d, const uint32_t* a, const uint32_t* b) {
    asm volatile("mma.sync.aligned.m16n8k16.row.col.f32.f16.f16.f32 "
        "{%0,%1,%2,%3}, {%4,%5,%6,%7}, {%8,%9}, {%0,%1,%2,%3};"
        : "+f"(d[0]), "+f"(d[1]), "+f"(d[2]), "+f"(d[3])
        : "r"(a[0]), "r"(a[1]), "r"(a[2]), "r"(a[3]), "r"(b[0]), "r"(b[1]));
}
__device__ __forceinline__ void cp_async16(uint32_t dst, const void* src) {
    asm volatile("cp.async.cg.shared.global [%0], [%1], 16;"
                 :: "r"(dst), "l"(src) : "memory");
}
#define CP_COMMIT() asm volatile("cp.async.commit_group;" ::: "memory")
#define CP_WAIT0()  asm volatile("cp.async.wait_group 0;" ::: "memory")

// accumulate 8 halves (uint4) into 8 float accumulators
__device__ __forceinline__ void acc8(float* a, uint4 r) {
    float2 f0 = __half22float2(*reinterpret_cast<__half2*>(&r.x));
    float2 f1 = __half22float2(*reinterpret_cast<__half2*>(&r.y));
    float2 f2 = __half22float2(*reinterpret_cast<__half2*>(&r.z));
    float2 f3 = __half22float2(*reinterpret_cast<__half2*>(&r.w));
    a[0] += f0.x; a[1] += f0.y; a[2] += f1.x; a[3] += f1.y;
    a[4] += f2.x; a[5] += f2.y; a[6] += f3.x; a[7] += f3.y;
}

// ---------------- setup + histogram (captures per-edge rank) ---------------
// Builds: deg/rank histogram, xh (fp16), BW1/BW2 (fp16 hi/lo, [n][512]).
__global__ void setup_hist_kernel(const int* __restrict__ ei32,
                                  const float* __restrict__ x,
                                  const float* __restrict__ Wl1, const float* __restrict__ Wr1,
                                  const float* __restrict__ Wl2, const float* __restrict__ Wr2,
                                  int* __restrict__ deg,
                                  int* __restrict__ rank,
                                  __half* __restrict__ BW1,
                                  __half* __restrict__ BW2,
                                  __half* __restrict__ xh) {
    int idx = blockIdx.x * blockDim.x + threadIdx.x;
    bool is64 = (ei32[1] == 0 && ei32[3] == 0 && ei32[5] == 0 && ei32[7] == 0);
    if (idx == 0) g_is64 = is64 ? 1 : 0;

    if (idx < N_EDGES / 4) {
        int i0 = idx * 4;
        int d0, d1, d2, d3;
        if (is64) {
            const longlong2* e = reinterpret_cast<const longlong2*>(
                (const long long*)ei32 + N_EDGES + i0);
            longlong2 a = e[0], b = e[1];
            d0 = (int)a.x; d1 = (int)a.y; d2 = (int)b.x; d3 = (int)b.y;
        } else {
            int4 a = *reinterpret_cast<const int4*>(ei32 + N_EDGES + i0);
            d0 = a.x; d1 = a.y; d2 = a.z; d3 = a.w;
        }
        int4 rk;
        rk.x = atomicAdd(&deg[d0], 1);
        rk.y = atomicAdd(&deg[d1], 1);
        rk.z = atomicAdd(&deg[d2], 1);
        rk.w = atomicAdd(&deg[d3], 1);
        *reinterpret_cast<int4*>(rank + i0) = rk;
    }

    if (idx < 256 * 512) {
        int n = idx / 512, kp = idx % 512;
        int seg = kp >> 8, k = kp & 255;
        // layer1: K = [mean(128) | x(128)] -> k<128: Wl1[k][n] else Wr1[k-128][n]
        float w1 = (k < 128) ? Wl1[k * 256 + n] : Wr1[(k - 128) * 256 + n];
        // layer2: N = [p(128) | z(128)] -> n<128: Wl2[k][n] else Wr2[k][n-128]
        float w2 = (n < 128) ? Wl2[k * 128 + n] : Wr2[k * 128 + (n - 128)];
        __half h1 = __float2half(w1);
        __half h2 = __float2half(w2);
        BW1[idx] = (seg == 1) ? __float2half(w1 - __half2float(h1)) : h1;
        BW2[idx] = (seg == 1) ? __float2half(w2 - __half2float(h2)) : h2;
    }
    if (idx < (N_NODES * IN_DIM) / 4) {
        float4 v = reinterpret_cast<const float4*>(x)[idx];
        __half2 a = __floats2half2_rn(v.x, v.y);
        __half2 b = __floats2half2_rn(v.z, v.w);
        reinterpret_cast<uint2*>(xh)[idx] =
            make_uint2(*reinterpret_cast<uint32_t*>(&a), *reinterpret_cast<uint32_t*>(&b));
    }
}

// ---------------- single-kernel decoupled-lookback scan --------------------
#define FLAG_AGG  (1ull << 62)
#define FLAG_INCL (2ull << 62)
#define VAL_MASK  ((1ull << 62) - 1)

__global__ __launch_bounds__(SCAN_BLK)
void scan_lookback(int* __restrict__ deg, int* __restrict__ rowoff) {
    __shared__ int sm[SCAN_BLK];
    __shared__ int s_base;
    int bid = blockIdx.x, tid = threadIdx.x;
    int i = bid * SCAN_BLK + tid;
    int v = (i < N_NODES) ? deg[i] : 0;
    if (i < N_NODES) deg[i] = 0;              // self-clean for next launch
    sm[tid] = v;
    __syncthreads();
    for (int off = 1; off < SCAN_BLK; off <<= 1) {
        int u = (tid >= off) ? sm[tid - off] : 0;
        __syncthreads();
        sm[tid] += u;
        __syncthreads();
    }
    int incl = sm[tid];
    int agg = sm[SCAN_BLK - 1];
    if (tid == 0) {
        if (bid == 0) {
            atomicExch(&g_state[0], FLAG_INCL | (unsigned long long)agg);
            s_base = 0;
        } else {
            atomicExch(&g_state[bid], FLAG_AGG | (unsigned long long)agg);
            int base = 0;
            for (int j = bid - 1; j >= 0; j--) {
                unsigned long long s;
                do { s = atomicAdd(&g_state[j], 0ull); } while ((s >> 62) == 0);
                base += (int)(s & VAL_MASK);
                if ((s >> 62) == 2) break;
            }
            s_base = base;
            atomicExch(&g_state[bid],
                       FLAG_INCL | (unsigned long long)(base + agg));
        }
    }
    __syncthreads();
    int base = s_base;
    if (i < N_NODES) rowoff[i] = base + incl - v;
    if (i == N_NODES - 1) rowoff[N_NODES] = base + incl;
}

// ---------------- fill CSR: atomic-free (rowoff + precomputed rank) --------
__global__ void fill_kernel(const void* __restrict__ ei,
                            const int* __restrict__ rank,
                            const int* __restrict__ rowoff,
                            int* __restrict__ csr) {
    int t = blockIdx.x * blockDim.x + threadIdx.x;
    if (t < N_SCAN_BLOCKS) g_state[t] = 0ull;   // reset lookback state
    int i0 = t * 2;
    if (i0 >= N_EDGES) return;
    int s0, s1, d0, d1;
    if (g_is64) {
        const long long* e = (const long long*)ei;
        longlong2 sp = *reinterpret_cast<const longlong2*>(e + i0);
        longlong2 dp = *reinterpret_cast<const longlong2*>(e + N_EDGES + i0);
        s0 = (int)sp.x; s1 = (int)sp.y; d0 = (int)dp.x; d1 = (int)dp.y;
    } else {
        const int* e = (const int*)ei;
        int2 sp = *reinterpret_cast<const int2*>(e + i0);
        int2 dp = *reinterpret_cast<const int2*>(e + N_EDGES + i0);
        s0 = sp.x; s1 = sp.y; d0 = dp.x; d1 = dp.y;
    }
    int2 rk = *reinterpret_cast<const int2*>(rank + i0);
    csr[rowoff[d0] + rk.x] = s0;
    csr[rowoff[d1] + rk.y] = s1;
}

// ---------------- gather-mean: warp per node, 2 neighbors per step ---------
// Writes the mean as a single fp16 plane (GEMM loop-1 A source).
__global__ void gather_mean_h(const __half* __restrict__ xh,
                              const int* __restrict__ row_off,
                              const int* __restrict__ csr,
                              __half* __restrict__ mh) {
    int node = blockIdx.x * (blockDim.x >> 5) + (threadIdx.x >> 5);
    int lane = threadIdx.x & 31;
    int half = lane >> 4, l16 = lane & 15;
    if (node >= N_NODES) return;
    int s0 = row_off[node], s1 = row_off[node + 1];
    const uint4* x4 = reinterpret_cast<const uint4*>(xh);   // row = 16 uint4
    float a[8] = {0.f, 0.f, 0.f, 0.f, 0.f, 0.f, 0.f, 0.f};
    for (int j = s0; j < s1; j += 32) {
        int n = min(32, s1 - j);
        int sj = (lane < n) ? csr[j + lane] : 0;
        int t = 0;
        for (; t + 8 <= n; t += 8) {
            uint4 raw[4];
#pragma unroll
            for (int u = 0; u < 4; u++) {
                int s = __shfl_sync(0xffffffffu, sj, t + u * 2 + half);
                raw[u] = x4[(size_t)s * 16 + l16];
            }
#pragma unroll
            for (int u = 0; u < 4; u++) acc8(a, raw[u]);
        }
        for (; t < n; t += 2) {
            int which = t + half;
            int s = __shfl_sync(0xffffffffu, sj, (which < n) ? which : 0);
            uint4 r = x4[(size_t)s * 16 + l16];
            if (which < n) acc8(a, r);
        }
    }
#pragma unroll
    for (int q = 0; q < 8; q++)
        a[q] += __shfl_xor_sync(0xffffffffu, a[q], 16);
    if (half == 0) {
        float inv = 1.0f / (float)max(s1 - s0, 1);
        __half2 p0 = __floats2half2_rn(a[0] * inv, a[1] * inv);
        __half2 p1 = __floats2half2_rn(a[2] * inv, a[3] * inv);
        __half2 p2 = __floats2half2_rn(a[4] * inv, a[5] * inv);
        __half2 p3 = __floats2half2_rn(a[6] * inv, a[7] * inv);
        size_t off = (size_t)node * 16 + l16;     // uint4 units (8 fp16)
        reinterpret_cast<uint4*>(mh)[off] =
            make_uint4(*reinterpret_cast<uint32_t*>(&p0), *reinterpret_cast<uint32_t*>(&p1),
                       *reinterpret_cast<uint32_t*>(&p2), *reinterpret_cast<uint32_t*>(&p3));
    }
}

// ---------------- final gather: warp per node, 2 neighbors per step --------
__global__ void gather_final_h(const __half* __restrict__ ph,
                               const float* __restrict__ z,
                               const int* __restrict__ row_off,
                               const int* __restrict__ csr,
                               float* __restrict__ out) {
    int node = blockIdx.x * (blockDim.x >> 5) + (threadIdx.x >> 5);
    int lane = threadIdx.x & 31;
    int half = lane >> 4, l16 = lane & 15;
    if (node >= N_NODES) return;
    int s0 = row_off[node], s1 = row_off[node + 1];
    const uint4* p4 = reinterpret_cast<const uint4*>(ph);   // row = 16 uint4
    float a[8] = {0.f, 0.f, 0.f, 0.f, 0.f, 0.f, 0.f, 0.f};
    for (int j = s0; j < s1; j += 32) {
        int n = min(32, s1 - j);
        int sj = (lane < n) ? csr[j + lane] : 0;
        int t = 0;
        for (; t + 8 <= n; t += 8) {
            uint4 raw[4];
#pragma unroll
            for (int u = 0; u < 4; u++) {
                int s = __shfl_sync(0xffffffffu, sj, t + u * 2 + half);
                raw[u] = p4[(size_t)s * 16 + l16];
            }
#pragma unroll
            for (int u = 0; u < 4; u++) acc8(a, raw[u]);
        }
        for (; t < n; t += 2) {
            int which = t + half;
            int s = __shfl_sync(0xffffffffu, sj, (which < n) ? which : 0);
            uint4 r = p4[(size_t)s * 16 + l16];
            if (which < n) acc8(a, r);
        }
    }
#pragma unroll
    for (int q = 0; q < 8; q++)
        a[q] += __shfl_xor_sync(0xffffffffu, a[q], 16);
    if (half == 0) {
        float inv = 1.0f / (float)max(s1 - s0, 1);
        size_t base = (size_t)node * 32 + l16 * 2;    // float4 units
        float4 z0 = reinterpret_cast<const float4*>(z)[base];
        float4 z1 = reinterpret_cast<const float4*>(z)[base + 1];
        float4 o0 = make_float4(a[0] * inv + z0.x, a[1] * inv + z0.y,
                                a[2] * inv + z0.z, a[3] * inv + z0.w);
        float4 o1 = make_float4(a[4] * inv + z1.x, a[5] * inv + z1.y,
                                a[6] * inv + z1.z, a[7] * inv + z1.w);
        reinterpret_cast<float4*>(out)[base] = o0;
        reinterpret_cast<float4*>(out)[base + 1] = o1;
    }
}

// ---------------- fused layer1+layer2 GEMM, 64-row tiles, 2 blocks/SM ------
// All fp16 operands, fp32 accum. 512 threads, 16 warps: wm = wid&1, wn = wid>>1.
// Loop1 (16 chunks): h = relu([mean|x]_f16 @ (B1hi|B1lo) + bl1) -> fp16 plane.
// Loop2 (16 chunks): (p|z) = h_f16 @ (B2hi|B2lo).
#define PL_H    0                  // 64 rows x 528B = 33792
#define OFF_SA  33792              // + buf*5120   (64 rows x 80B)
#define OFF_SB  44032              // + buf*20480  (256 rows x 80B)
#define FUSED_SMEM 84992           // ~83 KB -> 2 blocks/SM

__global__ __launch_bounds__(512, 2)
void sage_fused(const __half* __restrict__ Mh, const __half* __restrict__ Xh,
                const __half* __restrict__ BW1, const float* __restrict__ bl1,
                const __half* __restrict__ BW2, const float* __restrict__ bl2,
                float* __restrict__ z, __half* __restrict__ ph, int M)
{
    extern __shared__ __align__(16) char smem[];
    uint32_t sbase = smem_u32(smem);

    int tid = threadIdx.x;
    int lane = tid & 31, wid = tid >> 5;
    int wm = wid & 1, wn = wid >> 1;        // wm: 2x32 rows, wn: 8x32 cols
    int m0 = blockIdx.x * 64;

    int srow = tid >> 2, squad = tid & 3;   // A staging uses tid<256

    float acc[2][4][4];
#pragma unroll
    for (int i = 0; i < 2; i++)
#pragma unroll
        for (int j = 0; j < 4; j++)
#pragma unroll
            for (int q = 0; q < 4; q++) acc[i][j][q] = 0.f;

// A chunk cc (0..15): K-col = (cc&7)*32; source mean for k<128, x for k>=128.
#define CP_A1(cc, buf) do { \
    if (tid < 256) { \
        int kc = ((cc) & 7) * 32; \
        const __half* src_; int col_; \
        if (kc < 128) { src_ = Mh; col_ = kc; } \
        else          { src_ = Xh; col_ = kc - 128; } \
        cp_async16(sbase + OFF_SA + (buf) * 5120 + (uint32_t)srow * 80 + squad * 16, \
                   src_ + (size_t)(m0 + srow) * 128 + col_ + squad * 8); \
    } \
} while (0)

#define CP_B(BW, cc, buf) do { \
    _Pragma("unroll") \
    for (int i_ = 0; i_ < 2; i_++) { \
        int r_ = (tid >> 2) + i_ * 128; \
        cp_async16(sbase + OFF_SB + (buf) * 20480 + (uint32_t)r_ * 80 + squad * 16, \
                   (BW) + (size_t)r_ * 512 + (cc) * 32 + squad * 8); \
    } \
} while (0)

// B fragments: wn covers 32 cols = 2 x ldsm_x4 (16 n-rows each)
#define LOAD_FRAGS_B(buf, kh, bf) do { \
    _Pragma("unroll") \
    for (int np = 0; np < 2; np++) { \
        uint32_t q_[4]; \
        int r_ = wn * 32 + np * 16 + (lane & 7) + ((lane >> 4) & 1) * 8; \
        int cOff_ = ((lane >> 3) & 1) * 16; \
        ldsm_x4(q_, sbase + OFF_SB + (buf) * 20480 + (uint32_t)r_ * 80 + (kh) * 32 + cOff_); \
        (bf)[np * 2][0] = q_[0]; (bf)[np * 2][1] = q_[1]; \
        (bf)[np * 2 + 1][0] = q_[2]; (bf)[np * 2 + 1][1] = q_[3]; \
    } \
} while (0)

    // ========== loop 1: h = relu([mean|x]_f16 @ (B1hi|B1lo) + bl1) =========
    CP_A1(0, 0);
    CP_B(BW1, 0, 0);
    CP_COMMIT();
    CP_WAIT0();
    __syncthreads();

    for (int c = 0; c < 16; c++) {
        int cb = c & 1;
        if (c < 15) {
            CP_A1(c + 1, cb ^ 1);
            CP_B(BW1, c + 1, cb ^ 1);
            CP_COMMIT();
        }
#pragma unroll
        for (int kh = 0; kh < 2; kh++) {
            uint32_t af[2][4], bf[4][2];
#pragma unroll
            for (int mt = 0; mt < 2; mt++)
                ldsm_x4(af[mt], sbase + OFF_SA + cb * 5120
                        + (uint32_t)(wm * 32 + mt * 16 + (lane & 15)) * 80
                        + kh * 32 + (lane >> 4) * 16);
            LOAD_FRAGS_B(cb, kh, bf);
#pragma unroll
            for (int mt = 0; mt < 2; mt++)
#pragma unroll
                for (int nt = 0; nt < 4; nt++)
                    mma_f16(acc[mt][nt], af[mt], bf[nt]);
        }
        CP_WAIT0();
        __syncthreads();
    }

    // ---- epilogue 1: bias + relu -> fp16 plane in SMEM ----
    {
        int g = lane >> 2, t = lane & 3;
#pragma unroll
        for (int mt = 0; mt < 2; mt++) {
            int r0 = wm * 32 + mt * 16 + g;
#pragma unroll
            for (int nt = 0; nt < 4; nt++) {
                int col = wn * 32 + nt * 8 + t * 2;
                float bx = bl1[col], by = bl1[col + 1];
                float v0 = fmaxf(acc[mt][nt][0] + bx, 0.f);
                float v1 = fmaxf(acc[mt][nt][1] + by, 0.f);
                float v2 = fmaxf(acc[mt][nt][2] + bx, 0.f);
                float v3 = fmaxf(acc[mt][nt][3] + by, 0.f);
                __half2 p01 = __floats2half2_rn(v0, v1);
                __half2 p23 = __floats2half2_rn(v2, v3);
                *reinterpret_cast<__half2*>(smem + PL_H + r0 * 528 + col * 2) = p01;
                *reinterpret_cast<__half2*>(smem + PL_H + (r0 + 8) * 528 + col * 2) = p23;
            }
        }
    }

#pragma unroll
    for (int i = 0; i < 2; i++)
#pragma unroll
        for (int j = 0; j < 4; j++)
#pragma unroll
            for (int q = 0; q < 4; q++) acc[i][j][q] = 0.f;

    __syncthreads();

    // ========== loop 2: (p|z) = h_f16 @ (B2hi|B2lo)  (16 chunks) ===========
    CP_B(BW2, 0, 0);
    CP_COMMIT();
    CP_WAIT0();
    __syncthreads();

    for (int c = 0; c < 16; c++) {
        int cb = c & 1;
        if (c < 15) { CP_B(BW2, c + 1, cb ^ 1); CP_COMMIT(); }

        uint32_t koff = (uint32_t)(c & 7) * 64;
#pragma unroll
        for (int kh = 0; kh < 2; kh++) {
            uint32_t af[2][4], bf[4][2];
#pragma unroll
            for (int mt = 0; mt < 2; mt++)
                ldsm_x4(af[mt], sbase + PL_H
                        + (uint32_t)(wm * 32 + mt * 16 + (lane & 15)) * 528
                        + koff + kh * 32 + (lane >> 4) * 16);
            LOAD_FRAGS_B(cb, kh, bf);
#pragma unroll
            for (int mt = 0; mt < 2; mt++)
#pragma unroll
                for (int nt = 0; nt < 4; nt++)
                    mma_f16(acc[mt][nt], af[mt], bf[nt]);
        }
        CP_WAIT0();
        __syncthreads();
    }

    // ---- epilogue 2 ----
    {
        int g = lane >> 2, t = lane & 3;
#pragma unroll
        for (int mt = 0; mt < 2; mt++) {
            int r0 = m0 + wm * 32 + mt * 16 + g;
#pragma unroll
            for (int nt = 0; nt < 4; nt++) {
                int col = wn * 32 + nt * 8 + t * 2;
                if (col < 128) {
                    __half2 h01 = __floats2half2_rn(acc[mt][nt][0], acc[mt][nt][1]);
                    __half2 h23 = __floats2half2_rn(acc[mt][nt][2], acc[mt][nt][3]);
                    if (r0 < M)
                        *reinterpret_cast<__half2*>(ph + (size_t)r0 * 128 + col) = h01;
                    if (r0 + 8 < M)
                        *reinterpret_cast<__half2*>(ph + (size_t)(r0 + 8) * 128 + col) = h23;
                } else {
                    int zc = col - 128;
                    float bx = bl2[zc], by = bl2[zc + 1];
                    float v0 = acc[mt][nt][0] + bx, v1 = acc[mt][nt][1] + by;
                    float v2 = acc[mt][nt][2] + bx, v3 = acc[mt][nt][3] + by;
                    if (r0 < M)
                        *reinterpret_cast<float2*>(z + (size_t)r0 * 128 + zc) = make_float2(v0, v1);
                    if (r0 + 8 < M)
                        *reinterpret_cast<float2*>(z + (size_t)(r0 + 8) * 128 + zc) = make_float2(v2, v3);
                }
            }
        }
    }
}

// ---------------- launcher -------------------------------------------------
extern "C" void kernel_launch(void* const* d_in, const int* in_sizes, int n_in,
                              void* d_out, int out_size)
{
    const float* x   = (const float*)d_in[0];
    const void*  ei  = d_in[1];
    const float* Wl1 = (const float*)d_in[2];
    const float* bl1 = (const float*)d_in[3];
    const float* Wr1 = (const float*)d_in[4];
    const float* Wl2 = (const float*)d_in[5];
    const float* bl2 = (const float*)d_in[6];
    const float* Wr2 = (const float*)d_in[7];
    float* out = (float*)d_out;

    float *z;
    __half *ph, *xh, *mh, *BW1, *BW2;
    int *deg, *rank, *rowoff, *csr;
    cudaGetSymbolAddress((void**)&z,      g_z);
    cudaGetSymbolAddress((void**)&ph,     g_ph);
    cudaGetSymbolAddress((void**)&xh,     g_xh);
    cudaGetSymbolAddress((void**)&mh,     g_mh);
    cudaGetSymbolAddress((void**)&deg,    g_deg);
    cudaGetSymbolAddress((void**)&rank,   g_rank);
    cudaGetSymbolAddress((void**)&rowoff, g_rowoff);
    cudaGetSymbolAddress((void**)&csr,    g_csr);
    cudaGetSymbolAddress((void**)&BW1,    g_BW1);
    cudaGetSymbolAddress((void**)&BW2,    g_BW2);

    cudaFuncSetAttribute(sage_fused, cudaFuncAttributeMaxDynamicSharedMemorySize,
                         FUSED_SMEM);

    // ---- setup + histogram (captures per-edge rank) ----
    {
        int nthreads = (N_NODES * IN_DIM) / 4;
        setup_hist_kernel<<<(nthreads + 255) / 256, 256>>>(
            (const int*)ei, x, Wl1, Wr1, Wl2, Wr2, deg, rank, BW1, BW2, xh);
    }

    // ---- scan (single kernel, packed-state decoupled lookback) ----
    scan_lookback<<<N_SCAN_BLOCKS, SCAN_BLK>>>(deg, rowoff);

    // ---- fill CSR (atomic-free; also resets lookback state) ----
    fill_kernel<<<(N_EDGES / 2 + 255) / 256, 256>>>(ei, rank, rowoff, csr);

    // ---- layer 1 aggregation (writes fp16 mean plane) ----
    {
        int wpb = 8;
        int blocks = (N_NODES + wpb - 1) / wpb;
        gather_mean_h<<<blocks, wpb * 32>>>(xh, rowoff, csr, mh);
    }

    // ---- fused layer1+layer2 GEMM (all fp16, 64-row tiles, 2 blocks/SM) ----
    {
        int grid = (N_NODES + 63) / 64;
        sage_fused<<<grid, 512, FUSED_SMEM>>>(mh, xh, BW1, bl1, BW2, bl2,
                                              z, ph, N_NODES);
    }

    // ---- final aggregation ----
    {
        int wpb = 8;
        int blocks = (N_NODES + wpb - 1) / wpb;
        gather_final_h<<<blocks, wpb * 32>>>(ph, z, rowoff, csr, out);
    }
}